// round 3
// baseline (speedup 1.0000x reference)
#include <cuda_runtime.h>
#include <cuda_bf16.h>
#include <cstdint>

#define HID   2048
#define NH    16
#define HD    128
#define QKV_N 2304
#define BB    2
#define SS    2048
#define MTOT  4096

// ---------------------------------------------------------------------------
// Scratch (no allocs allowed)
// ---------------------------------------------------------------------------
__device__ float g_qkv[(size_t)MTOT * QKV_N];
__device__ float g_att[(size_t)MTOT * HID];
__device__ __nv_bfloat16 g_ah[(size_t)MTOT * HID];
__device__ __nv_bfloat16 g_al[(size_t)MTOT * HID];
__device__ __nv_bfloat16 g_bh[(size_t)QKV_N * HID];
__device__ __nv_bfloat16 g_bl[(size_t)QKV_N * HID];

// ---------------------------------------------------------------------------
// helpers
// ---------------------------------------------------------------------------
__device__ __forceinline__ uint32_t smem_u32(const void* p) {
    uint32_t a;
    asm("{ .reg .u64 t; cvta.to.shared.u64 t, %1; cvt.u32.u64 %0, t; }" : "=r"(a) : "l"(p));
    return a;
}
#define CP_ASYNC16(s, g) \
    asm volatile("cp.async.cg.shared.global [%0], [%1], 16;" :: "r"(s), "l"(g) : "memory")
#define CP_COMMIT() asm volatile("cp.async.commit_group;" ::: "memory")
#define CP_WAIT1()  asm volatile("cp.async.wait_group 1;" ::: "memory")
#define CP_WAIT0()  asm volatile("cp.async.wait_group 0;" ::: "memory")

#define LDM_X4(r0, r1, r2, r3, a) \
    asm volatile("ldmatrix.sync.aligned.m8n8.x4.shared.b16 {%0,%1,%2,%3}, [%4];" \
        : "=r"(r0), "=r"(r1), "=r"(r2), "=r"(r3) : "r"(a))

#define MMA16816(c, av, bv0, bv1) \
    asm volatile("mma.sync.aligned.m16n8k16.row.col.f32.bf16.bf16.f32 " \
        "{%0,%1,%2,%3},{%4,%5,%6,%7},{%8,%9},{%0,%1,%2,%3};" \
        : "+f"((c)[0]), "+f"((c)[1]), "+f"((c)[2]), "+f"((c)[3]) \
        : "r"((av)[0]), "r"((av)[1]), "r"((av)[2]), "r"((av)[3]), "r"(bv0), "r"(bv1))

__device__ __forceinline__ uint32_t pack_bf2(__nv_bfloat16 a, __nv_bfloat16 b) {
    return ((uint32_t)__bfloat16_as_ushort(b) << 16) | (uint32_t)__bfloat16_as_ushort(a);
}

// ---------------------------------------------------------------------------
// fp32 -> (hi, lo) bf16 split
// ---------------------------------------------------------------------------
__global__ void convert_split(const float* __restrict__ in,
                              __nv_bfloat16* __restrict__ hi,
                              __nv_bfloat16* __restrict__ lo, int n4) {
    int i = blockIdx.x * blockDim.x + threadIdx.x;
    int st = gridDim.x * blockDim.x;
    for (; i < n4; i += st) {
        float4 v = ((const float4*)in)[i];
        __nv_bfloat16 h0 = __float2bfloat16(v.x), h1 = __float2bfloat16(v.y);
        __nv_bfloat16 h2 = __float2bfloat16(v.z), h3 = __float2bfloat16(v.w);
        __nv_bfloat16 l0 = __float2bfloat16(v.x - __bfloat162float(h0));
        __nv_bfloat16 l1 = __float2bfloat16(v.y - __bfloat162float(h1));
        __nv_bfloat16 l2 = __float2bfloat16(v.z - __bfloat162float(h2));
        __nv_bfloat16 l3 = __float2bfloat16(v.w - __bfloat162float(h3));
        uint2 ph; ph.x = pack_bf2(h0, h1); ph.y = pack_bf2(h2, h3);
        uint2 pl; pl.x = pack_bf2(l0, l1); pl.y = pack_bf2(l2, l3);
        ((uint2*)hi)[i] = ph;
        ((uint2*)lo)[i] = pl;
    }
}

// W[K,N] row-major -> [N,K] K-major hi/lo
__global__ void transpose_split(const float* __restrict__ W,
                                __nv_bfloat16* __restrict__ hi,
                                __nv_bfloat16* __restrict__ lo, int K, int N) {
    __shared__ float t[32][33];
    int n0 = blockIdx.x * 32, k0 = blockIdx.y * 32;
    int tx = threadIdx.x, ty = threadIdx.y;
#pragma unroll
    for (int j = 0; j < 4; j++)
        t[ty + 8 * j][tx] = W[(size_t)(k0 + ty + 8 * j) * N + n0 + tx];
    __syncthreads();
#pragma unroll
    for (int j = 0; j < 4; j++) {
        float v = t[tx][ty + 8 * j];
        __nv_bfloat16 h = __float2bfloat16(v);
        __nv_bfloat16 l = __float2bfloat16(v - __bfloat162float(h));
        size_t off = (size_t)(n0 + ty + 8 * j) * K + k0 + tx;
        hi[off] = h;
        lo[off] = l;
    }
}

// ---------------------------------------------------------------------------
// HMMA bf16-split GEMM: C = Ah Bh^T + Ah Bl^T + Al Bh^T + bias
// A:[M,K] K-major, B:[N,K] K-major. CTA 128x128x32, 8 warps (2m x 4n).
// ---------------------------------------------------------------------------
#define PITCHB 80                    // bytes per smem row (40 bf16)
#define TILEB  (128 * PITCHB)        // 10240 per operand tile
#define STAGEB (4 * TILEB)           // Ah, Al, Bh, Bl
#define GEMM_SMEM (2 * STAGEB)       // 81920

__device__ __forceinline__ void issue_stage(
    uint32_t smb, int st,
    const __nv_bfloat16* __restrict__ Ah, const __nv_bfloat16* __restrict__ Al,
    const __nv_bfloat16* __restrict__ Bh, const __nv_bfloat16* __restrict__ Bl,
    int m0, int n0, int k0, int K, int tid)
{
    const __nv_bfloat16* srcs[4] = {Ah + (size_t)m0 * K, Al + (size_t)m0 * K,
                                    Bh + (size_t)n0 * K, Bl + (size_t)n0 * K};
    uint32_t base = smb + st * STAGEB;
#pragma unroll
    for (int it = 0; it < 8; it++) {
        int idx = tid + it * 256;          // 0..2047
        int tile = idx >> 9;               // 0..3
        int id2  = idx & 511;
        int row  = id2 >> 2;
        int c16  = id2 & 3;                // 16-byte chunk within row
        uint32_t sa = base + tile * TILEB + row * PITCHB + c16 * 16;
        const void* g = srcs[tile] + (size_t)row * K + k0 + c16 * 8;
        CP_ASYNC16(sa, g);
    }
    CP_COMMIT();
}

__global__ __launch_bounds__(256, 1) void gemm_split_mma(
    const __nv_bfloat16* __restrict__ Ah, const __nv_bfloat16* __restrict__ Al,
    const __nv_bfloat16* __restrict__ Bh, const __nv_bfloat16* __restrict__ Bl,
    const float* __restrict__ bias, float* __restrict__ C,
    int M, int N, int K)
{
    extern __shared__ char sm[];
    const uint32_t smb = smem_u32(sm);
    const int tid = threadIdx.x;
    const int wid = tid >> 5, lane = tid & 31;
    const int m0 = blockIdx.y * 128, n0 = blockIdx.x * 128;
    const int warp_m = wid & 1, warp_n = wid >> 1;
    const int m0w = warp_m * 64, n0w = warp_n * 32;
    const int NC = K >> 5;                 // 32-wide k chunks

    float acc[4][4][4];
#pragma unroll
    for (int i = 0; i < 4; i++)
#pragma unroll
        for (int j = 0; j < 4; j++)
#pragma unroll
            for (int r = 0; r < 4; r++) acc[i][j][r] = 0.f;

    // ldmatrix lane addressing: lr = row within 16, lc = k-half (16B)
    const int lr = lane & 15, lc = lane >> 4;
    const uint32_t aoff = (uint32_t)(m0w + lr) * PITCHB + lc * 16;
    const uint32_t boff = (uint32_t)(128 + 128 + n0w + lr) * PITCHB + lc * 16; // Bh tile idx 2

    issue_stage(smb, 0, Ah, Al, Bh, Bl, m0, n0, 0, K, tid);

    for (int c = 0; c < NC; c++) {
        const int s = c & 1;
        if (c + 1 < NC) {
            issue_stage(smb, 1 - s, Ah, Al, Bh, Bl, m0, n0, (c + 1) << 5, K, tid);
            CP_WAIT1();
        } else {
            CP_WAIT0();
        }
        __syncthreads();

        const uint32_t sa_hi = smb + s * STAGEB + aoff;            // Ah tile 0
        const uint32_t sa_lo = sa_hi + TILEB;                      // Al tile 1
        const uint32_t sb_hi = smb + s * STAGEB + boff;            // Bh
        const uint32_t sb_lo = sb_hi + TILEB;                      // Bl

#pragma unroll
        for (int ks = 0; ks < 2; ks++) {
            const uint32_t kb = ks * 32;
            uint32_t ah[4][4], al[4][4], bh[2][4], bl[2][4];
#pragma unroll
            for (int mt = 0; mt < 4; mt++) {
                LDM_X4(ah[mt][0], ah[mt][1], ah[mt][2], ah[mt][3],
                       sa_hi + kb + mt * (16 * PITCHB));
                LDM_X4(al[mt][0], al[mt][1], al[mt][2], al[mt][3],
                       sa_lo + kb + mt * (16 * PITCHB));
            }
#pragma unroll
            for (int g = 0; g < 2; g++) {
                LDM_X4(bh[g][0], bh[g][1], bh[g][2], bh[g][3],
                       sb_hi + kb + g * (16 * PITCHB));
                LDM_X4(bl[g][0], bl[g][1], bl[g][2], bl[g][3],
                       sb_lo + kb + g * (16 * PITCHB));
            }
            // x4 on B: regs {n0-7/k0-7, n8-15/k0-7, n0-7/k8-15, n8-15/k8-15}
#pragma unroll
            for (int mt = 0; mt < 4; mt++) {
#pragma unroll
                for (int nt = 0; nt < 4; nt++) {
                    const int g = nt >> 1, h = nt & 1;
                    MMA16816(acc[mt][nt], ah[mt], bh[g][h], bh[g][h + 2]);
                    MMA16816(acc[mt][nt], ah[mt], bl[g][h], bl[g][h + 2]);
                    MMA16816(acc[mt][nt], al[mt], bh[g][h], bh[g][h + 2]);
                }
            }
        }
        __syncthreads();
    }

    // epilogue: c frag rows l/4 and l/4+8, cols 2*(l%4)
    const int cr = lane >> 2, cc = (lane & 3) * 2;
#pragma unroll
    for (int mt = 0; mt < 4; mt++) {
#pragma unroll
        for (int nt = 0; nt < 4; nt++) {
            int col = n0 + n0w + nt * 8 + cc;
            float b0 = bias[col], b1 = bias[col + 1];
            int r0 = m0 + m0w + mt * 16 + cr;
            float2 v0 = {acc[mt][nt][0] + b0, acc[mt][nt][1] + b1};
            float2 v1 = {acc[mt][nt][2] + b0, acc[mt][nt][3] + b1};
            *(float2*)(C + (size_t)r0 * N + col)       = v0;
            *(float2*)(C + (size_t)(r0 + 8) * N + col) = v1;
        }
    }
}

// ---------------------------------------------------------------------------
// MQA flash attention (causal), fp32 — unchanged (passing R1 version)
// ---------------------------------------------------------------------------
#define BQ  64
#define BKV 64
#define QP  132
#define KP  132
#define PP  65

__global__ __launch_bounds__(256, 1) void mqa_kernel(
    const float* __restrict__ qkv, float* __restrict__ out)
{
    extern __shared__ float smf[];
    float* Qs = smf;
    float* Ks = Qs + BQ * QP;
    float* Vs = Ks + BKV * KP;
    float* Ps = Vs + BKV * HD;
    float* Cs = Ps + BQ * PP;
    float* Ls = Cs + BQ;

    const int qt  = blockIdx.x;
    const int h   = blockIdx.y;
    const int b   = blockIdx.z;
    const int tid = threadIdx.x;
    const int q0  = qt * BQ;
    const float scale = 0.088388347648318447f;

    for (int i = tid; i < BQ * HD / 4; i += 256) {
        int r  = i >> 5;
        int c4 = (i & 31) * 4;
        float4 v = *(const float4*)(qkv + (size_t)(b * SS + q0 + r) * QKV_N + h * HD + c4);
        float* dst = Qs + r * QP + c4;
        dst[0] = v.x; dst[1] = v.y; dst[2] = v.z; dst[3] = v.w;
    }

    const int lane4 = tid & 3;
    const int rA    = tid >> 2;
    float m_i = -1e30f, l_i = 0.f;

    const int tx = tid % 16;
    const int ty = tid / 16;
    const int row0 = ty * 4;
    float acc[4][8];
#pragma unroll
    for (int i = 0; i < 4; i++)
#pragma unroll
        for (int j = 0; j < 8; j++) acc[i][j] = 0.f;

    for (int j = 0; j <= qt; j++) {
        __syncthreads();
        const int k0 = j * BKV;

        for (int i = tid; i < BKV * HD / 4; i += 256) {
            int r  = i >> 5;
            int c4 = (i & 31) * 4;
            const float* base = qkv + (size_t)(b * SS + k0 + r) * QKV_N;
            float4 kk = *(const float4*)(base + HID + c4);
            float* dk = Ks + r * KP + c4;
            dk[0] = kk.x; dk[1] = kk.y; dk[2] = kk.z; dk[3] = kk.w;
            float4 vv = *(const float4*)(base + HID + HD + c4);
            *(float4*)(Vs + r * HD + c4) = vv;
        }
        __syncthreads();

        {
            float s[16];
#pragma unroll
            for (int ci = 0; ci < 16; ci++) s[ci] = 0.f;
            const float* Qrow = Qs + rA * QP;
#pragma unroll 4
            for (int k4 = 0; k4 < 32; k4++) {
                float4 q = *(const float4*)(Qrow + 4 * k4);
#pragma unroll
                for (int ci = 0; ci < 16; ci++) {
                    int cc = lane4 + 4 * ci;
                    float4 kk = *(const float4*)(Ks + cc * KP + 4 * k4);
                    s[ci] += q.x * kk.x + q.y * kk.y + q.z * kk.z + q.w * kk.w;
                }
            }
            const bool diag = (j == qt);
#pragma unroll
            for (int ci = 0; ci < 16; ci++) {
                int cc = lane4 + 4 * ci;
                float v = s[ci] * scale;
                if (diag && (k0 + cc > q0 + rA)) v = -1e30f;
                s[ci] = v;
            }
            float mloc = s[0];
#pragma unroll
            for (int ci = 1; ci < 16; ci++) mloc = fmaxf(mloc, s[ci]);
            mloc = fmaxf(mloc, __shfl_xor_sync(0xffffffffu, mloc, 1));
            mloc = fmaxf(mloc, __shfl_xor_sync(0xffffffffu, mloc, 2));
            float mnew = fmaxf(m_i, mloc);
            float corr = __expf(m_i - mnew);
            float psum = 0.f;
#pragma unroll
            for (int ci = 0; ci < 16; ci++) {
                float p = __expf(s[ci] - mnew);
                Ps[rA * PP + lane4 + 4 * ci] = p;
                psum += p;
            }
            psum += __shfl_xor_sync(0xffffffffu, psum, 1);
            psum += __shfl_xor_sync(0xffffffffu, psum, 2);
            l_i = l_i * corr + psum;
            m_i = mnew;
            if (lane4 == 0) { Cs[rA] = corr; Ls[rA] = l_i; }
        }
        __syncthreads();

        {
            float cr[4];
#pragma unroll
            for (int i = 0; i < 4; i++) cr[i] = Cs[row0 + i];
#pragma unroll
            for (int i = 0; i < 4; i++)
#pragma unroll
                for (int jj = 0; jj < 8; jj++) acc[i][jj] *= cr[i];

#pragma unroll 4
            for (int c = 0; c < BKV; c++) {
                float p0 = Ps[(row0 + 0) * PP + c];
                float p1 = Ps[(row0 + 1) * PP + c];
                float p2 = Ps[(row0 + 2) * PP + c];
                float p3 = Ps[(row0 + 3) * PP + c];
                float4 v0 = *(const float4*)(Vs + c * HD + tx * 8);
                float4 v1 = *(const float4*)(Vs + c * HD + tx * 8 + 4);
                float vv[8] = {v0.x, v0.y, v0.z, v0.w, v1.x, v1.y, v1.z, v1.w};
#pragma unroll
                for (int jj = 0; jj < 8; jj++) {
                    acc[0][jj] += p0 * vv[jj];
                    acc[1][jj] += p1 * vv[jj];
                    acc[2][jj] += p2 * vv[jj];
                    acc[3][jj] += p3 * vv[jj];
                }
            }
        }
    }

#pragma unroll
    for (int i = 0; i < 4; i++) {
        float linv = 1.f / Ls[row0 + i];
        int qg = q0 + row0 + i;
        float4 o0, o1;
        o0.x = acc[i][0] * linv; o0.y = acc[i][1] * linv;
        o0.z = acc[i][2] * linv; o0.w = acc[i][3] * linv;
        o1.x = acc[i][4] * linv; o1.y = acc[i][5] * linv;
        o1.z = acc[i][6] * linv; o1.w = acc[i][7] * linv;
        float* dst = out + (size_t)(b * SS + qg) * HID + h * HD + tx * 8;
        *(float4*)dst       = o0;
        *(float4*)(dst + 4) = o1;
    }
}

// ---------------------------------------------------------------------------
// kernel_launch
// ---------------------------------------------------------------------------
extern "C" void kernel_launch(void* const* d_in, const int* in_sizes, int n_in,
                              void* d_out, int out_size)
{
    const float* hidden = (const float*)d_in[0];
    const float* w1     = (const float*)d_in[2];
    const float* b1     = (const float*)d_in[3];
    const float* w2     = (const float*)d_in[4];
    const float* b2     = (const float*)d_in[5];
    float* out          = (float*)d_out;

    float *qkv, *att;
    __nv_bfloat16 *ah, *al, *bh, *bl;
    cudaGetSymbolAddress((void**)&qkv, g_qkv);
    cudaGetSymbolAddress((void**)&att, g_att);
    cudaGetSymbolAddress((void**)&ah, g_ah);
    cudaGetSymbolAddress((void**)&al, g_al);
    cudaGetSymbolAddress((void**)&bh, g_bh);
    cudaGetSymbolAddress((void**)&bl, g_bl);

    cudaFuncSetAttribute(gemm_split_mma, cudaFuncAttributeMaxDynamicSharedMemorySize, GEMM_SMEM);

    // ---- QKV projection ----
    convert_split<<<1024, 256>>>(hidden, ah, al, MTOT * HID / 4);
    transpose_split<<<dim3(QKV_N / 32, HID / 32), dim3(32, 8)>>>(w1, bh, bl, HID, QKV_N);
    gemm_split_mma<<<dim3(QKV_N / 128, MTOT / 128), 256, GEMM_SMEM>>>(
        ah, al, bh, bl, b1, qkv, MTOT, QKV_N, HID);

    // ---- attention ----
    size_t smem = (size_t)(BQ * QP + BKV * KP + BKV * HD + BQ * PP + 2 * BQ) * sizeof(float);
    cudaFuncSetAttribute(mqa_kernel, cudaFuncAttributeMaxDynamicSharedMemorySize, (int)smem);
    mqa_kernel<<<dim3(SS / BQ, NH, BB), 256, smem>>>(qkv, att);

    // ---- output projection ----
    convert_split<<<1024, 256>>>(att, ah, al, MTOT * HID / 4);
    transpose_split<<<dim3(HID / 32, HID / 32), dim3(32, 8)>>>(w2, bh, bl, HID, HID);
    gemm_split_mma<<<dim3(HID / 128, MTOT / 128), 256, GEMM_SMEM>>>(
        ah, al, bh, bl, b2, out, MTOT, HID, HID);
}

// round 5
// speedup vs baseline: 1.1599x; 1.1599x over previous
#include <cuda_runtime.h>
#include <cstdint>

#define HID   2048
#define NH    16
#define HD    128
#define QKV_N 2304
#define BB    2
#define SS    2048
#define MTOT  4096

// Scratch (no allocs allowed)
__device__ float g_qkv[(size_t)MTOT * QKV_N];
__device__ float g_att[(size_t)MTOT * HID];

// ---------------------------------------------------------------------------
// packed f32x2 helpers (FFMA2 — PTX fma.rn.f32x2, sm_100+ baseline feature)
// ---------------------------------------------------------------------------
__device__ __forceinline__ void ffma2(uint64_t& d, uint64_t a, uint64_t b) {
    asm("fma.rn.f32x2 %0, %1, %2, %0;" : "+l"(d) : "l"(a), "l"(b));
}
__device__ __forceinline__ void fmul2(uint64_t& d, uint64_t a) {
    asm("mul.rn.f32x2 %0, %0, %1;" : "+l"(d) : "l"(a));
}
__device__ __forceinline__ uint64_t pack2(float x, float y) {
    uint64_t r; asm("mov.b64 %0, {%1,%2};" : "=l"(r) : "f"(x), "f"(y)); return r;
}
__device__ __forceinline__ uint64_t dup2(float x) { return pack2(x, x); }
__device__ __forceinline__ float2 unpack2(uint64_t v) {
    float2 r; asm("mov.b64 {%0,%1}, %2;" : "=f"(r.x), "=f"(r.y) : "l"(v)); return r;
}

// ---------------------------------------------------------------------------
// SGEMM + bias, fp32 with packed FFMA2 math.
// BM=BN=128, BK=16, 256 threads, 8x8 microtile (as 8x4 f32x2 pairs).
// ---------------------------------------------------------------------------
__global__ __launch_bounds__(256, 2) void sgemm_bias(
    const float* __restrict__ A, const float* __restrict__ Bm,
    const float* __restrict__ bias, float* __restrict__ C,
    int M, int N, int K)
{
    __shared__ float As[16 * 132];   // transposed: As[k][m], padded
    __shared__ float Bs[16 * 128];   // Bs[k][n]

    const int bx = blockIdx.x;
    const int by = blockIdx.y;
    const int tid = threadIdx.x;
    const int tx = tid % 16;
    const int ty = tid / 16;

    const float* Ab = A + (size_t)by * 128 * K;
    const float* Bb = Bm + (size_t)bx * 128;

    uint64_t acc2[8][4];
#pragma unroll
    for (int i = 0; i < 8; i++)
#pragma unroll
        for (int j = 0; j < 4; j++) acc2[i][j] = 0ull;

    for (int k0 = 0; k0 < K; k0 += 16) {
#pragma unroll
        for (int it = 0; it < 2; it++) {
            int idx = tid + it * 256;
            int ar = idx >> 2;
            int ac = (idx & 3) * 4;
            float4 av = *(const float4*)(Ab + (size_t)ar * K + k0 + ac);
            As[(ac + 0) * 132 + ar] = av.x;
            As[(ac + 1) * 132 + ar] = av.y;
            As[(ac + 2) * 132 + ar] = av.z;
            As[(ac + 3) * 132 + ar] = av.w;
            int br = idx >> 5;
            int bc = (idx & 31) * 4;
            float4 bv = *(const float4*)(Bb + (size_t)(k0 + br) * N + bc);
            *(float4*)&Bs[br * 128 + bc] = bv;
        }
        __syncthreads();

#pragma unroll
        for (int k = 0; k < 16; k++) {
            float4 a0 = *(const float4*)&As[k * 132 + ty * 8];
            float4 a1 = *(const float4*)&As[k * 132 + ty * 8 + 4];
            float4 b0 = *(const float4*)&Bs[k * 128 + tx * 8];
            float4 b1 = *(const float4*)&Bs[k * 128 + tx * 8 + 4];
            uint64_t bp[4];
            bp[0] = pack2(b0.x, b0.y); bp[1] = pack2(b0.z, b0.w);
            bp[2] = pack2(b1.x, b1.y); bp[3] = pack2(b1.z, b1.w);
            float av[8] = {a0.x, a0.y, a0.z, a0.w, a1.x, a1.y, a1.z, a1.w};
#pragma unroll
            for (int i = 0; i < 8; i++) {
                uint64_t ad = dup2(av[i]);
#pragma unroll
                for (int j = 0; j < 4; j++) ffma2(acc2[i][j], ad, bp[j]);
            }
        }
        __syncthreads();
    }

    const int col = bx * 128 + tx * 8;
    float4 bi0 = *(const float4*)(bias + col);
    float4 bi1 = *(const float4*)(bias + col + 4);
    float bb[8] = {bi0.x, bi0.y, bi0.z, bi0.w, bi1.x, bi1.y, bi1.z, bi1.w};
#pragma unroll
    for (int i = 0; i < 8; i++) {
        int row = by * 128 + ty * 8 + i;
        float o[8];
#pragma unroll
        for (int j = 0; j < 4; j++) {
            float2 t = unpack2(acc2[i][j]);
            o[2 * j] = t.x + bb[2 * j];
            o[2 * j + 1] = t.y + bb[2 * j + 1];
        }
        *(float4*)(C + (size_t)row * N + col)     = make_float4(o[0], o[1], o[2], o[3]);
        *(float4*)(C + (size_t)row * N + col + 4) = make_float4(o[4], o[5], o[6], o[7]);
    }
}

// ---------------------------------------------------------------------------
// MQA flash attention (causal), fp32 + FFMA2.
// Grid: (S/128, NH, B), 512 threads. Q tile 128x128, KV tiles 64x128.
// Phase A: 4 lanes/row, 16 cols each, packed over k-pairs.
// Phase B: thread owns 4 rows x 8 dims (4 f32x2 pairs).
// ---------------------------------------------------------------------------
#define BQ  128
#define BKV 64
#define QP  132
#define KP  132
#define PP  65

__global__ __launch_bounds__(512, 1) void mqa_kernel(
    const float* __restrict__ qkv, float* __restrict__ out)
{
    extern __shared__ float smf[];
    float* Qs = smf;                       // 128*132
    float* Ks = Qs + BQ * QP;              // 64*132
    float* Vs = Ks + BKV * KP;             // 64*128
    float* Ps = Vs + BKV * HD;             // 128*65
    float* Cs = Ps + BQ * PP;              // 128
    float* Ls = Cs + BQ;                   // 128

    const int qt  = (int)gridDim.x - 1 - (int)blockIdx.x;  // heavy tiles first
    const int h   = blockIdx.y;
    const int b   = blockIdx.z;
    const int tid = threadIdx.x;
    const int q0  = qt * BQ;
    const float scale = 0.088388347648318447f;

    // load Q tile
    for (int i = tid; i < BQ * HD / 4; i += 512) {
        int r  = i >> 5;
        int c4 = (i & 31) * 4;
        float4 v = *(const float4*)(qkv + (size_t)(b * SS + q0 + r) * QKV_N + h * HD + c4);
        float* dst = Qs + r * QP + c4;
        dst[0] = v.x; dst[1] = v.y; dst[2] = v.z; dst[3] = v.w;
    }

    const int lane4 = tid & 3;
    const int rA    = tid >> 2;            // 0..127
    float m_i = -1e30f, l_i = 0.f;

    const int tx = tid & 15;
    const int ty = tid >> 4;               // 0..31
    const int row0 = ty * 4;
    uint64_t acc2[4][4];
#pragma unroll
    for (int i = 0; i < 4; i++)
#pragma unroll
        for (int j = 0; j < 4; j++) acc2[i][j] = 0ull;

    const int jmax = 2 * qt + 1;
    for (int j = 0; j <= jmax; j++) {
        __syncthreads();                   // prev phase B done with Ks/Vs/Ps
        const int k0 = j * BKV;

        for (int i = tid; i < BKV * HD / 4; i += 512) {
            int r  = i >> 5;
            int c4 = (i & 31) * 4;
            const float* base = qkv + (size_t)(b * SS + k0 + r) * QKV_N;
            float4 kk = *(const float4*)(base + HID + c4);
            float* dk = Ks + r * KP + c4;
            dk[0] = kk.x; dk[1] = kk.y; dk[2] = kk.z; dk[3] = kk.w;
            float4 vv = *(const float4*)(base + HID + HD + c4);
            *(float4*)(Vs + r * HD + c4) = vv;
        }
        __syncthreads();

        // -------- phase A: scores (packed over k) + online softmax --------
        {
            uint64_t s2[16];
#pragma unroll
            for (int ci = 0; ci < 16; ci++) s2[ci] = 0ull;
            const float* Qrow = Qs + rA * QP;
#pragma unroll 2
            for (int k4 = 0; k4 < 32; k4++) {
                float4 q = *(const float4*)(Qrow + 4 * k4);
                uint64_t qp0 = pack2(q.x, q.y);
                uint64_t qp1 = pack2(q.z, q.w);
#pragma unroll
                for (int ci = 0; ci < 16; ci++) {
                    int cc = lane4 + 4 * ci;
                    float4 kk = *(const float4*)(Ks + cc * KP + 4 * k4);
                    ffma2(s2[ci], qp0, pack2(kk.x, kk.y));
                    ffma2(s2[ci], qp1, pack2(kk.z, kk.w));
                }
            }
            const bool diag = (j >= 2 * qt);
            float s[16];
#pragma unroll
            for (int ci = 0; ci < 16; ci++) {
                int cc = lane4 + 4 * ci;
                float2 t = unpack2(s2[ci]);
                float v = (t.x + t.y) * scale;
                if (diag && (k0 + cc > q0 + rA)) v = -1e30f;
                s[ci] = v;
            }
            float mloc = s[0];
#pragma unroll
            for (int ci = 1; ci < 16; ci++) mloc = fmaxf(mloc, s[ci]);
            mloc = fmaxf(mloc, __shfl_xor_sync(0xffffffffu, mloc, 1));
            mloc = fmaxf(mloc, __shfl_xor_sync(0xffffffffu, mloc, 2));
            float mnew = fmaxf(m_i, mloc);
            float corr = __expf(m_i - mnew);
            float psum = 0.f;
#pragma unroll
            for (int ci = 0; ci < 16; ci++) {
                float p = __expf(s[ci] - mnew);
                Ps[rA * PP + lane4 + 4 * ci] = p;
                psum += p;
            }
            psum += __shfl_xor_sync(0xffffffffu, psum, 1);
            psum += __shfl_xor_sync(0xffffffffu, psum, 2);
            l_i = l_i * corr + psum;
            m_i = mnew;
            if (lane4 == 0) { Cs[rA] = corr; Ls[rA] = l_i; }
        }
        __syncthreads();

        // -------- phase B: acc = acc*corr + P @ V  (packed over dims) -----
        {
#pragma unroll
            for (int i = 0; i < 4; i++) {
                uint64_t cd = dup2(Cs[row0 + i]);
#pragma unroll
                for (int jj = 0; jj < 4; jj++) fmul2(acc2[i][jj], cd);
            }
#pragma unroll 2
            for (int c = 0; c < BKV; c++) {
                uint64_t p0 = dup2(Ps[(row0 + 0) * PP + c]);
                uint64_t p1 = dup2(Ps[(row0 + 1) * PP + c]);
                uint64_t p2 = dup2(Ps[(row0 + 2) * PP + c]);
                uint64_t p3 = dup2(Ps[(row0 + 3) * PP + c]);
                float4 v0 = *(const float4*)(Vs + c * HD + tx * 8);
                float4 v1 = *(const float4*)(Vs + c * HD + tx * 8 + 4);
                uint64_t vp[4];
                vp[0] = pack2(v0.x, v0.y); vp[1] = pack2(v0.z, v0.w);
                vp[2] = pack2(v1.x, v1.y); vp[3] = pack2(v1.z, v1.w);
#pragma unroll
                for (int jj = 0; jj < 4; jj++) {
                    ffma2(acc2[0][jj], p0, vp[jj]);
                    ffma2(acc2[1][jj], p1, vp[jj]);
                    ffma2(acc2[2][jj], p2, vp[jj]);
                    ffma2(acc2[3][jj], p3, vp[jj]);
                }
            }
        }
    }

    // epilogue
#pragma unroll
    for (int i = 0; i < 4; i++) {
        float linv = 1.f / Ls[row0 + i];
        int qg = q0 + row0 + i;
        float o[8];
#pragma unroll
        for (int jj = 0; jj < 4; jj++) {
            float2 t = unpack2(acc2[i][jj]);
            o[2 * jj] = t.x * linv;
            o[2 * jj + 1] = t.y * linv;
        }
        float* dst = out + (size_t)(b * SS + qg) * HID + h * HD + tx * 8;
        *(float4*)dst       = make_float4(o[0], o[1], o[2], o[3]);
        *(float4*)(dst + 4) = make_float4(o[4], o[5], o[6], o[7]);
    }
}

// ---------------------------------------------------------------------------
// kernel_launch
// ---------------------------------------------------------------------------
extern "C" void kernel_launch(void* const* d_in, const int* in_sizes, int n_in,
                              void* d_out, int out_size)
{
    const float* hidden = (const float*)d_in[0];
    const float* w1     = (const float*)d_in[2];
    const float* b1     = (const float*)d_in[3];
    const float* w2     = (const float*)d_in[4];
    const float* b2     = (const float*)d_in[5];
    float* out          = (float*)d_out;

    float *qkv, *att;
    cudaGetSymbolAddress((void**)&qkv, g_qkv);
    cudaGetSymbolAddress((void**)&att, g_att);

    // QKV projection
    dim3 g1(QKV_N / 128, MTOT / 128);
    sgemm_bias<<<g1, 256>>>(hidden, w1, b1, qkv, MTOT, QKV_N, HID);

    // attention
    size_t smem = (size_t)(BQ * QP + BKV * KP + BKV * HD + BQ * PP + 2 * BQ) * sizeof(float);
    cudaFuncSetAttribute(mqa_kernel, cudaFuncAttributeMaxDynamicSharedMemorySize, (int)smem);
    mqa_kernel<<<dim3(SS / BQ, NH, BB), 512, smem>>>(qkv, att);

    // output projection
    dim3 g2(HID / 128, MTOT / 128);
    sgemm_bias<<<g2, 256>>>(att, w2, b2, out, MTOT, HID, HID);
}

// round 10
// speedup vs baseline: 1.4576x; 1.2566x over previous
#include <cuda_runtime.h>
#include <cstdint>

#define HID   2048
#define NH    16
#define HD    128
#define QKV_N 2304
#define BB    2
#define SS    2048
#define MTOT  4096

// Scratch (no allocs allowed)
__device__ float g_qkv[(size_t)MTOT * QKV_N];
__device__ float g_att[(size_t)MTOT * HID];

// ---------------------------------------------------------------------------
// SGEMM + bias, fp32, double-buffered (BK=32, reg prefetch, 1 sync per block)
// BM=BN=128, 256 threads, 8x8 microtile.
// ---------------------------------------------------------------------------
#define GBK 32
#define AS_STRIDE (GBK * 132)     // 4224 floats per stage
#define BS_STRIDE (GBK * 128)     // 4096 floats per stage
#define SGEMM_SMEM ((2 * AS_STRIDE + 2 * BS_STRIDE) * 4)   // 66560 B

__global__ __launch_bounds__(256, 2) void sgemm_bias(
    const float* __restrict__ A, const float* __restrict__ Bm,
    const float* __restrict__ bias, float* __restrict__ C,
    int M, int N, int K)
{
    extern __shared__ float sg[];
    float* As = sg;                       // 2 stages, transposed [k][m], pad 132
    float* Bs = sg + 2 * AS_STRIDE;       // 2 stages, [k][n]

    const int bx = blockIdx.x;
    const int by = blockIdx.y;
    const int tid = threadIdx.x;
    const int tx = tid % 16;
    const int ty = tid / 16;

    const float* Ab = A + (size_t)by * 128 * K;
    const float* Bb = Bm + (size_t)bx * 128;

    // per-thread load coords (4 chunks each for A and B)
    const int ar = tid >> 3;              // A row 0..31 (+32/it)
    const int ac = (tid & 7) * 4;         // A k offset
    const int br = tid >> 5;              // B k row 0..7 (+8/it)
    const int bc = (tid & 31) * 4;        // B n offset

    float4 pa[4], pb[4];

    // prologue: load block 0
#pragma unroll
    for (int it = 0; it < 4; it++) {
        pa[it] = *(const float4*)(Ab + (size_t)(ar + it * 32) * K + ac);
        pb[it] = *(const float4*)(Bb + (size_t)(br + it * 8) * N + bc);
    }
#pragma unroll
    for (int it = 0; it < 4; it++) {
        As[(ac + 0) * 132 + ar + it * 32] = pa[it].x;
        As[(ac + 1) * 132 + ar + it * 32] = pa[it].y;
        As[(ac + 2) * 132 + ar + it * 32] = pa[it].z;
        As[(ac + 3) * 132 + ar + it * 32] = pa[it].w;
        *(float4*)&Bs[(br + it * 8) * 128 + bc] = pb[it];
    }
    __syncthreads();

    float acc[8][8];
#pragma unroll
    for (int i = 0; i < 8; i++)
#pragma unroll
        for (int j = 0; j < 8; j++) acc[i][j] = 0.f;

    const int NC = K / GBK;
    for (int c = 0; c < NC; c++) {
        const int s = c & 1;
        if (c + 1 < NC) {
            const int k0 = (c + 1) * GBK;
#pragma unroll
            for (int it = 0; it < 4; it++) {
                pa[it] = *(const float4*)(Ab + (size_t)(ar + it * 32) * K + k0 + ac);
                pb[it] = *(const float4*)(Bb + (size_t)(k0 + br + it * 8) * N + bc);
            }
        }
        const float* Asb = As + s * AS_STRIDE;
        const float* Bsb = Bs + s * BS_STRIDE;
#pragma unroll 8
        for (int k = 0; k < GBK; k++) {
            float4 a0 = *(const float4*)&Asb[k * 132 + ty * 8];
            float4 a1 = *(const float4*)&Asb[k * 132 + ty * 8 + 4];
            float4 b0 = *(const float4*)&Bsb[k * 128 + tx * 8];
            float4 b1 = *(const float4*)&Bsb[k * 128 + tx * 8 + 4];
            float av[8] = {a0.x, a0.y, a0.z, a0.w, a1.x, a1.y, a1.z, a1.w};
            float bv[8] = {b0.x, b0.y, b0.z, b0.w, b1.x, b1.y, b1.z, b1.w};
#pragma unroll
            for (int i = 0; i < 8; i++)
#pragma unroll
                for (int j = 0; j < 8; j++)
                    acc[i][j] += av[i] * bv[j];
        }
        if (c + 1 < NC) {
            float* Asn = As + (1 - s) * AS_STRIDE;
            float* Bsn = Bs + (1 - s) * BS_STRIDE;
#pragma unroll
            for (int it = 0; it < 4; it++) {
                Asn[(ac + 0) * 132 + ar + it * 32] = pa[it].x;
                Asn[(ac + 1) * 132 + ar + it * 32] = pa[it].y;
                Asn[(ac + 2) * 132 + ar + it * 32] = pa[it].z;
                Asn[(ac + 3) * 132 + ar + it * 32] = pa[it].w;
                *(float4*)&Bsn[(br + it * 8) * 128 + bc] = pb[it];
            }
        }
        __syncthreads();
    }

    const int col = bx * 128 + tx * 8;
    float4 bi0 = *(const float4*)(bias + col);
    float4 bi1 = *(const float4*)(bias + col + 4);
#pragma unroll
    for (int i = 0; i < 8; i++) {
        int row = by * 128 + ty * 8 + i;
        float4 o0, o1;
        o0.x = acc[i][0] + bi0.x; o0.y = acc[i][1] + bi0.y;
        o0.z = acc[i][2] + bi0.z; o0.w = acc[i][3] + bi0.w;
        o1.x = acc[i][4] + bi1.x; o1.y = acc[i][5] + bi1.y;
        o1.z = acc[i][6] + bi1.z; o1.w = acc[i][7] + bi1.w;
        *(float4*)(C + (size_t)row * N + col)     = o0;
        *(float4*)(C + (size_t)row * N + col + 4) = o1;
    }
}

// ---------------------------------------------------------------------------
// MQA flash attention (causal), fp32, GEMM-style register tiling.
// Grid (S/128, NH, B), 512 threads. Q/K/V tiles 128x128.
// Phase A: warp w owns rows 8w..8w+7, lane owns cols lane+32j (j=0..3):
//          8x4 microtile, Q broadcast, conflict-free K loads. Softmax state in
//          registers; P overwrites the K smem tile.
// Phase B: thread owns rows 4ry..+3, dims [4dx..4dx+3] and [64+4dx..+3].
// ---------------------------------------------------------------------------
#define APAD 132
#define ATT_SMEM ((128 * APAD * 2 + 128 * HD + 256) * 4)   // 201728 B

__global__ __launch_bounds__(512, 1) void mqa_kernel(
    const float* __restrict__ qkv, float* __restrict__ out)
{
    extern __shared__ float smf[];
    float* Qs = smf;                   // 128*132
    float* Ks = Qs + 128 * APAD;       // 128*132 : K tile, then P tile
    float* Vs = Ks + 128 * APAD;       // 128*128
    float* Cs = Vs + 128 * HD;         // 128
    float* Ls = Cs + 128;              // 128

    const int qt = (int)gridDim.x - 1 - (int)blockIdx.x;   // heavy tiles first
    const int h = blockIdx.y, b = blockIdx.z;
    const int tid = threadIdx.x;
    const int q0 = qt * 128;
    const float scale = 0.088388347648318447f;   // 1/sqrt(128)

    // load Q tile
    for (int i = tid; i < 128 * 32; i += 512) {
        int r = i >> 5, c4 = (i & 31) * 4;
        *(float4*)(Qs + r * APAD + c4) =
            *(const float4*)(qkv + (size_t)(b * SS + q0 + r) * QKV_N + h * HD + c4);
    }

    const int wid = tid >> 5, lane = tid & 31;   // phase A ids
    const int ry = tid >> 4, dx = tid & 15;      // phase B ids

    float m_i[8], l_i[8];
#pragma unroll
    for (int i = 0; i < 8; i++) { m_i[i] = -1e30f; l_i[i] = 0.f; }

    float acc[4][8];
#pragma unroll
    for (int i = 0; i < 4; i++)
#pragma unroll
        for (int j = 0; j < 8; j++) acc[i][j] = 0.f;

    for (int j = 0; j <= qt; j++) {
        __syncthreads();                 // prev phase B done with Ks(P)/Vs
        const int k0 = j * 128;

        for (int i = tid; i < 128 * 32; i += 512) {
            int r = i >> 5, c4 = (i & 31) * 4;
            const float* base = qkv + (size_t)(b * SS + k0 + r) * QKV_N;
            *(float4*)(Ks + r * APAD + c4) = *(const float4*)(base + HID + c4);
            *(float4*)(Vs + r * HD + c4)   = *(const float4*)(base + HID + HD + c4);
        }
        __syncthreads();

        // -------- phase A: scores 8x4 microtile --------
        float s[8][4];
#pragma unroll
        for (int i = 0; i < 8; i++)
#pragma unroll
            for (int jj = 0; jj < 4; jj++) s[i][jj] = 0.f;

#pragma unroll 4
        for (int k4 = 0; k4 < 32; k4++) {
            float4 kk[4];
#pragma unroll
            for (int jj = 0; jj < 4; jj++)
                kk[jj] = *(const float4*)(Ks + (lane + 32 * jj) * APAD + 4 * k4);
#pragma unroll
            for (int i = 0; i < 8; i++) {
                float4 q = *(const float4*)(Qs + (8 * wid + i) * APAD + 4 * k4);
#pragma unroll
                for (int jj = 0; jj < 4; jj++)
                    s[i][jj] += q.x * kk[jj].x + q.y * kk[jj].y +
                                q.z * kk[jj].z + q.w * kk[jj].w;
            }
        }

        const bool diag = (j == qt);
        float corr[8];
#pragma unroll
        for (int i = 0; i < 8; i++) {
            const int row = q0 + 8 * wid + i;
#pragma unroll
            for (int jj = 0; jj < 4; jj++) {
                float v = s[i][jj] * scale;
                if (diag && (k0 + lane + 32 * jj > row)) v = -1e30f;
                s[i][jj] = v;
            }
            float ml = fmaxf(fmaxf(s[i][0], s[i][1]), fmaxf(s[i][2], s[i][3]));
            ml = fmaxf(ml, __shfl_xor_sync(0xffffffffu, ml, 1));
            ml = fmaxf(ml, __shfl_xor_sync(0xffffffffu, ml, 2));
            ml = fmaxf(ml, __shfl_xor_sync(0xffffffffu, ml, 4));
            ml = fmaxf(ml, __shfl_xor_sync(0xffffffffu, ml, 8));
            ml = fmaxf(ml, __shfl_xor_sync(0xffffffffu, ml, 16));
            float mnew = fmaxf(m_i[i], ml);
            corr[i] = __expf(m_i[i] - mnew);
            float ps = 0.f;
#pragma unroll
            for (int jj = 0; jj < 4; jj++) {
                float p = __expf(s[i][jj] - mnew);
                s[i][jj] = p;
                ps += p;
            }
            ps += __shfl_xor_sync(0xffffffffu, ps, 1);
            ps += __shfl_xor_sync(0xffffffffu, ps, 2);
            ps += __shfl_xor_sync(0xffffffffu, ps, 4);
            ps += __shfl_xor_sync(0xffffffffu, ps, 8);
            ps += __shfl_xor_sync(0xffffffffu, ps, 16);
            l_i[i] = l_i[i] * corr[i] + ps;
            m_i[i] = mnew;
        }
        __syncthreads();                 // all K reads complete

        // store P into Ks (overwrite K); publish corr + running sums
#pragma unroll
        for (int i = 0; i < 8; i++)
#pragma unroll
            for (int jj = 0; jj < 4; jj++)
                Ks[(8 * wid + i) * APAD + lane + 32 * jj] = s[i][jj];
        if (lane == 0) {
#pragma unroll
            for (int i = 0; i < 8; i++) {
                Cs[8 * wid + i] = corr[i];
                Ls[8 * wid + i] = l_i[i];
            }
        }
        __syncthreads();

        // -------- phase B: acc = acc*corr + P @ V --------
#pragma unroll
        for (int i = 0; i < 4; i++) {
            float cr = Cs[4 * ry + i];
#pragma unroll
            for (int jj = 0; jj < 8; jj++) acc[i][jj] *= cr;
        }
#pragma unroll 4
        for (int c = 0; c < 128; c++) {
            float4 v0 = *(const float4*)(Vs + c * HD + 4 * dx);
            float4 v1 = *(const float4*)(Vs + c * HD + 64 + 4 * dx);
#pragma unroll
            for (int i = 0; i < 4; i++) {
                float p = Ks[(4 * ry + i) * APAD + c];
                acc[i][0] += p * v0.x; acc[i][1] += p * v0.y;
                acc[i][2] += p * v0.z; acc[i][3] += p * v0.w;
                acc[i][4] += p * v1.x; acc[i][5] += p * v1.y;
                acc[i][6] += p * v1.z; acc[i][7] += p * v1.w;
            }
        }
    }

    // epilogue
#pragma unroll
    for (int i = 0; i < 4; i++) {
        float linv = 1.f / Ls[4 * ry + i];
        int qg = q0 + 4 * ry + i;
        float* dst = out + (size_t)(b * SS + qg) * HID + h * HD;
        *(float4*)(dst + 4 * dx) = make_float4(
            acc[i][0] * linv, acc[i][1] * linv, acc[i][2] * linv, acc[i][3] * linv);
        *(float4*)(dst + 64 + 4 * dx) = make_float4(
            acc[i][4] * linv, acc[i][5] * linv, acc[i][6] * linv, acc[i][7] * linv);
    }
}

// ---------------------------------------------------------------------------
// kernel_launch
// ---------------------------------------------------------------------------
extern "C" void kernel_launch(void* const* d_in, const int* in_sizes, int n_in,
                              void* d_out, int out_size)
{
    const float* hidden = (const float*)d_in[0];
    const float* w1     = (const float*)d_in[2];
    const float* b1     = (const float*)d_in[3];
    const float* w2     = (const float*)d_in[4];
    const float* b2     = (const float*)d_in[5];
    float* out          = (float*)d_out;

    float *qkv, *att;
    cudaGetSymbolAddress((void**)&qkv, g_qkv);
    cudaGetSymbolAddress((void**)&att, g_att);

    cudaFuncSetAttribute(sgemm_bias, cudaFuncAttributeMaxDynamicSharedMemorySize, SGEMM_SMEM);
    cudaFuncSetAttribute(mqa_kernel, cudaFuncAttributeMaxDynamicSharedMemorySize, ATT_SMEM);

    // QKV projection
    dim3 g1(QKV_N / 128, MTOT / 128);
    sgemm_bias<<<g1, 256, SGEMM_SMEM>>>(hidden, w1, b1, qkv, MTOT, QKV_N, HID);

    // attention
    mqa_kernel<<<dim3(SS / 128, NH, BB), 512, ATT_SMEM>>>(qkv, att);

    // output projection
    dim3 g2(HID / 128, MTOT / 128);
    sgemm_bias<<<g2, 256, SGEMM_SMEM>>>(att, w2, b2, out, MTOT, HID, HID);
}

// round 11
// speedup vs baseline: 1.5071x; 1.0340x over previous
#include <cuda_runtime.h>
#include <cstdint>

#define HID   2048
#define NH    16
#define HD    128
#define QKV_N 2304
#define BB    2
#define SS    2048
#define MTOT  4096

// Scratch (no allocs allowed)
__device__ float g_qkv[(size_t)MTOT * QKV_N];
__device__ float g_att[(size_t)MTOT * HID];

// ---------------------------------------------------------------------------
// cp.async helpers
// ---------------------------------------------------------------------------
__device__ __forceinline__ uint32_t smem_u32(const void* p) {
    uint32_t a;
    asm("{ .reg .u64 t; cvta.to.shared.u64 t, %1; cvt.u32.u64 %0, t; }" : "=r"(a) : "l"(p));
    return a;
}
__device__ __forceinline__ void cp16(uint32_t s, const void* g) {
    asm volatile("cp.async.cg.shared.global [%0], [%1], 16;" :: "r"(s), "l"(g) : "memory");
}
#define CP_COMMIT() asm volatile("cp.async.commit_group;" ::: "memory")
#define CP_WAIT2()  asm volatile("cp.async.wait_group 2;" ::: "memory")

// ---------------------------------------------------------------------------
// SGEMM + bias, fp32, cp.async 4-stage pipeline, BK=16, 256 threads, 8x8 tile.
// Stage layout: A as float4 As4[4][128]  (k-chunk-major, no transpose needed)
//               B as float  Bs[16][128]
// ---------------------------------------------------------------------------
#define GBK 16
#define STG_BYTES 16384            // 8192 (A) + 8192 (B)
#define NSTG 4
#define SGEMM_SMEM (NSTG * STG_BYTES)   // 65536

__device__ __forceinline__ void issue_blk(
    uint32_t smb, int slot, const float* __restrict__ Ab,
    const float* __restrict__ Bb, int k0, int N, int K, int tid)
{
    const uint32_t base = smb + (uint32_t)slot * STG_BYTES;
#pragma unroll
    for (int it = 0; it < 2; it++) {
        int c = tid + it * 256;            // 0..511
        // A chunk: row = c>>2 (0..127), kc = c&3 (16B k-chunk)
        int arow = c >> 2, akc = c & 3;
        cp16(base + akc * 2048 + arow * 16,
             Ab + (size_t)arow * K + k0 + akc * 4);
        // B chunk: krow = c>>5 (0..15), col16 = c&31
        int bkr = c >> 5, bcol = c & 31;
        cp16(base + 8192 + bkr * 512 + bcol * 16,
             Bb + (size_t)(k0 + bkr) * N + bcol * 4);
    }
    CP_COMMIT();
}

__global__ __launch_bounds__(256, 2) void sgemm_bias(
    const float* __restrict__ A, const float* __restrict__ Bm,
    const float* __restrict__ bias, float* __restrict__ C,
    int M, int N, int K)
{
    extern __shared__ char sg[];
    const uint32_t smb = smem_u32(sg);

    const int bx = blockIdx.x;
    const int by = blockIdx.y;
    const int tid = threadIdx.x;
    const int tx = tid % 16;
    const int ty = tid / 16;

    const float* Ab = A + (size_t)by * 128 * K;
    const float* Bb = Bm + (size_t)bx * 128;

    float acc[8][8];
#pragma unroll
    for (int i = 0; i < 8; i++)
#pragma unroll
        for (int j = 0; j < 8; j++) acc[i][j] = 0.f;

    const int NC = K / GBK;

    // prologue: stages for blocks 0,1,2
    issue_blk(smb, 0, Ab, Bb, 0, N, K, tid);
    issue_blk(smb, 1, Ab, Bb, GBK, N, K, tid);
    issue_blk(smb, 2, Ab, Bb, 2 * GBK, N, K, tid);

    for (int c = 0; c < NC; c++) {
        CP_WAIT2();                 // block c's group complete
        __syncthreads();            // all threads done reading slot (c-1)%4

        if (c + 3 < NC) {
            issue_blk(smb, (c + 3) & 3, Ab, Bb, (c + 3) * GBK, N, K, tid);
        } else {
            CP_COMMIT();            // keep group count uniform
        }

        const int slot = c & 3;
        const float4* As4 = (const float4*)(sg + (size_t)slot * STG_BYTES);   // [4][128]
        const float*  Bsf = (const float*)(sg + (size_t)slot * STG_BYTES + 8192); // [16][128]

#pragma unroll
        for (int k4 = 0; k4 < 4; k4++) {
            float4 af[8];
#pragma unroll
            for (int i = 0; i < 8; i++)
                af[i] = As4[k4 * 128 + ty * 8 + i];
#pragma unroll
            for (int kk = 0; kk < 4; kk++) {
                const int k = k4 * 4 + kk;
                float4 b0 = *(const float4*)&Bsf[k * 128 + tx * 8];
                float4 b1 = *(const float4*)&Bsf[k * 128 + tx * 8 + 4];
                float bv[8] = {b0.x, b0.y, b0.z, b0.w, b1.x, b1.y, b1.z, b1.w};
#pragma unroll
                for (int i = 0; i < 8; i++) {
                    float a = (kk == 0) ? af[i].x : (kk == 1) ? af[i].y
                             : (kk == 2) ? af[i].z : af[i].w;
#pragma unroll
                    for (int j = 0; j < 8; j++)
                        acc[i][j] += a * bv[j];
                }
            }
        }
    }

    const int col = bx * 128 + tx * 8;
    float4 bi0 = *(const float4*)(bias + col);
    float4 bi1 = *(const float4*)(bias + col + 4);
#pragma unroll
    for (int i = 0; i < 8; i++) {
        int row = by * 128 + ty * 8 + i;
        float4 o0, o1;
        o0.x = acc[i][0] + bi0.x; o0.y = acc[i][1] + bi0.y;
        o0.z = acc[i][2] + bi0.z; o0.w = acc[i][3] + bi0.w;
        o1.x = acc[i][4] + bi1.x; o1.y = acc[i][5] + bi1.y;
        o1.z = acc[i][6] + bi1.z; o1.w = acc[i][7] + bi1.w;
        *(float4*)(C + (size_t)row * N + col)     = o0;
        *(float4*)(C + (size_t)row * N + col + 4) = o1;
    }
}

// ---------------------------------------------------------------------------
// MQA flash attention (causal), fp32, GEMM-style register tiling.
// (unchanged from R10 — proven at ~1290 us)
// ---------------------------------------------------------------------------
#define APAD 132
#define ATT_SMEM ((128 * APAD * 2 + 128 * HD + 256) * 4)   // 201728 B

__global__ __launch_bounds__(512, 1) void mqa_kernel(
    const float* __restrict__ qkv, float* __restrict__ out)
{
    extern __shared__ float smf[];
    float* Qs = smf;                   // 128*132
    float* Ks = Qs + 128 * APAD;       // 128*132 : K tile, then P tile
    float* Vs = Ks + 128 * APAD;       // 128*128
    float* Cs = Vs + 128 * HD;         // 128
    float* Ls = Cs + 128;              // 128

    const int qt = (int)gridDim.x - 1 - (int)blockIdx.x;   // heavy tiles first
    const int h = blockIdx.y, b = blockIdx.z;
    const int tid = threadIdx.x;
    const int q0 = qt * 128;
    const float scale = 0.088388347648318447f;   // 1/sqrt(128)

    // load Q tile
    for (int i = tid; i < 128 * 32; i += 512) {
        int r = i >> 5, c4 = (i & 31) * 4;
        *(float4*)(Qs + r * APAD + c4) =
            *(const float4*)(qkv + (size_t)(b * SS + q0 + r) * QKV_N + h * HD + c4);
    }

    const int wid = tid >> 5, lane = tid & 31;   // phase A ids
    const int ry = tid >> 4, dx = tid & 15;      // phase B ids

    float m_i[8], l_i[8];
#pragma unroll
    for (int i = 0; i < 8; i++) { m_i[i] = -1e30f; l_i[i] = 0.f; }

    float acc[4][8];
#pragma unroll
    for (int i = 0; i < 4; i++)
#pragma unroll
        for (int j = 0; j < 8; j++) acc[i][j] = 0.f;

    for (int j = 0; j <= qt; j++) {
        __syncthreads();                 // prev phase B done with Ks(P)/Vs
        const int k0 = j * 128;

        for (int i = tid; i < 128 * 32; i += 512) {
            int r = i >> 5, c4 = (i & 31) * 4;
            const float* base = qkv + (size_t)(b * SS + k0 + r) * QKV_N;
            *(float4*)(Ks + r * APAD + c4) = *(const float4*)(base + HID + c4);
            *(float4*)(Vs + r * HD + c4)   = *(const float4*)(base + HID + HD + c4);
        }
        __syncthreads();

        // -------- phase A: scores 8x4 microtile --------
        float s[8][4];
#pragma unroll
        for (int i = 0; i < 8; i++)
#pragma unroll
            for (int jj = 0; jj < 4; jj++) s[i][jj] = 0.f;

#pragma unroll 4
        for (int k4 = 0; k4 < 32; k4++) {
            float4 kk[4];
#pragma unroll
            for (int jj = 0; jj < 4; jj++)
                kk[jj] = *(const float4*)(Ks + (lane + 32 * jj) * APAD + 4 * k4);
#pragma unroll
            for (int i = 0; i < 8; i++) {
                float4 q = *(const float4*)(Qs + (8 * wid + i) * APAD + 4 * k4);
#pragma unroll
                for (int jj = 0; jj < 4; jj++)
                    s[i][jj] += q.x * kk[jj].x + q.y * kk[jj].y +
                                q.z * kk[jj].z + q.w * kk[jj].w;
            }
        }

        const bool diag = (j == qt);
        float corr[8];
#pragma unroll
        for (int i = 0; i < 8; i++) {
            const int row = q0 + 8 * wid + i;
#pragma unroll
            for (int jj = 0; jj < 4; jj++) {
                float v = s[i][jj] * scale;
                if (diag && (k0 + lane + 32 * jj > row)) v = -1e30f;
                s[i][jj] = v;
            }
            float ml = fmaxf(fmaxf(s[i][0], s[i][1]), fmaxf(s[i][2], s[i][3]));
            ml = fmaxf(ml, __shfl_xor_sync(0xffffffffu, ml, 1));
            ml = fmaxf(ml, __shfl_xor_sync(0xffffffffu, ml, 2));
            ml = fmaxf(ml, __shfl_xor_sync(0xffffffffu, ml, 4));
            ml = fmaxf(ml, __shfl_xor_sync(0xffffffffu, ml, 8));
            ml = fmaxf(ml, __shfl_xor_sync(0xffffffffu, ml, 16));
            float mnew = fmaxf(m_i[i], ml);
            corr[i] = __expf(m_i[i] - mnew);
            float ps = 0.f;
#pragma unroll
            for (int jj = 0; jj < 4; jj++) {
                float p = __expf(s[i][jj] - mnew);
                s[i][jj] = p;
                ps += p;
            }
            ps += __shfl_xor_sync(0xffffffffu, ps, 1);
            ps += __shfl_xor_sync(0xffffffffu, ps, 2);
            ps += __shfl_xor_sync(0xffffffffu, ps, 4);
            ps += __shfl_xor_sync(0xffffffffu, ps, 8);
            ps += __shfl_xor_sync(0xffffffffu, ps, 16);
            l_i[i] = l_i[i] * corr[i] + ps;
            m_i[i] = mnew;
        }
        __syncthreads();                 // all K reads complete

        // store P into Ks (overwrite K); publish corr + running sums
#pragma unroll
        for (int i = 0; i < 8; i++)
#pragma unroll
            for (int jj = 0; jj < 4; jj++)
                Ks[(8 * wid + i) * APAD + lane + 32 * jj] = s[i][jj];
        if (lane == 0) {
#pragma unroll
            for (int i = 0; i < 8; i++) {
                Cs[8 * wid + i] = corr[i];
                Ls[8 * wid + i] = l_i[i];
            }
        }
        __syncthreads();

        // -------- phase B: acc = acc*corr + P @ V --------
#pragma unroll
        for (int i = 0; i < 4; i++) {
            float cr = Cs[4 * ry + i];
#pragma unroll
            for (int jj = 0; jj < 8; jj++) acc[i][jj] *= cr;
        }
#pragma unroll 4
        for (int c = 0; c < 128; c++) {
            float4 v0 = *(const float4*)(Vs + c * HD + 4 * dx);
            float4 v1 = *(const float4*)(Vs + c * HD + 64 + 4 * dx);
#pragma unroll
            for (int i = 0; i < 4; i++) {
                float p = Ks[(4 * ry + i) * APAD + c];
                acc[i][0] += p * v0.x; acc[i][1] += p * v0.y;
                acc[i][2] += p * v0.z; acc[i][3] += p * v0.w;
                acc[i][4] += p * v1.x; acc[i][5] += p * v1.y;
                acc[i][6] += p * v1.z; acc[i][7] += p * v1.w;
            }
        }
    }

    // epilogue
#pragma unroll
    for (int i = 0; i < 4; i++) {
        float linv = 1.f / Ls[4 * ry + i];
        int qg = q0 + 4 * ry + i;
        float* dst = out + (size_t)(b * SS + qg) * HID + h * HD;
        *(float4*)(dst + 4 * dx) = make_float4(
            acc[i][0] * linv, acc[i][1] * linv, acc[i][2] * linv, acc[i][3] * linv);
        *(float4*)(dst + 64 + 4 * dx) = make_float4(
            acc[i][4] * linv, acc[i][5] * linv, acc[i][6] * linv, acc[i][7] * linv);
    }
}

// ---------------------------------------------------------------------------
// kernel_launch
// ---------------------------------------------------------------------------
extern "C" void kernel_launch(void* const* d_in, const int* in_sizes, int n_in,
                              void* d_out, int out_size)
{
    const float* hidden = (const float*)d_in[0];
    const float* w1     = (const float*)d_in[2];
    const float* b1     = (const float*)d_in[3];
    const float* w2     = (const float*)d_in[4];
    const float* b2     = (const float*)d_in[5];
    float* out          = (float*)d_out;

    float *qkv, *att;
    cudaGetSymbolAddress((void**)&qkv, g_qkv);
    cudaGetSymbolAddress((void**)&att, g_att);

    cudaFuncSetAttribute(sgemm_bias, cudaFuncAttributeMaxDynamicSharedMemorySize, SGEMM_SMEM);
    cudaFuncSetAttribute(mqa_kernel, cudaFuncAttributeMaxDynamicSharedMemorySize, ATT_SMEM);

    // QKV projection
    dim3 g1(QKV_N / 128, MTOT / 128);
    sgemm_bias<<<g1, 256, SGEMM_SMEM>>>(hidden, w1, b1, qkv, MTOT, QKV_N, HID);

    // attention
    mqa_kernel<<<dim3(SS / 128, NH, BB), 512, ATT_SMEM>>>(qkv, att);

    // output projection
    dim3 g2(HID / 128, MTOT / 128);
    sgemm_bias<<<g2, 256, SGEMM_SMEM>>>(att, w2, b2, out, MTOT, HID, HID);
}

// round 14
// speedup vs baseline: 1.5322x; 1.0166x over previous
#include <cuda_runtime.h>
#include <cstdint>

#define HID   2048
#define NH    16
#define HD    128
#define QKV_N 2304
#define BB    2
#define SS    2048
#define MTOT  4096

// Scratch (no allocs allowed)
__device__ float g_qkv[(size_t)MTOT * QKV_N];
__device__ float g_att[(size_t)MTOT * HID];

// ---------------------------------------------------------------------------
// helpers
// ---------------------------------------------------------------------------
__device__ __forceinline__ uint32_t smem_u32(const void* p) {
    uint32_t a;
    asm("{ .reg .u64 t; cvta.to.shared.u64 t, %1; cvt.u32.u64 %0, t; }" : "=r"(a) : "l"(p));
    return a;
}
__device__ __forceinline__ void cp16(uint32_t s, const void* g) {
    asm volatile("cp.async.cg.shared.global [%0], [%1], 16;" :: "r"(s), "l"(g) : "memory");
}
#define CP_COMMIT() asm volatile("cp.async.commit_group;" ::: "memory")
#define CP_WAIT1()  asm volatile("cp.async.wait_group 1;" ::: "memory")
#define CP_WAIT0()  asm volatile("cp.async.wait_group 0;" ::: "memory")

// ---------------------------------------------------------------------------
// SGEMM with bias (R1-proven variant): BM=BN=128, BK=16, 256 thr, 8x8 tile.
// ---------------------------------------------------------------------------
__global__ __launch_bounds__(256) void sgemm_bias(
    const float* __restrict__ A, const float* __restrict__ Bm,
    const float* __restrict__ bias, float* __restrict__ C,
    int M, int N, int K)
{
    __shared__ float As[16 * 132];   // transposed: As[k][m], padded
    __shared__ float Bs[16 * 128];   // Bs[k][n]

    const int bx = blockIdx.x;
    const int by = blockIdx.y;
    const int tid = threadIdx.x;
    const int tx = tid % 16;
    const int ty = tid / 16;

    const float* Ab = A + (size_t)by * 128 * K;
    const float* Bb = Bm + (size_t)bx * 128;

    float acc[8][8];
#pragma unroll
    for (int i = 0; i < 8; i++)
#pragma unroll
        for (int j = 0; j < 8; j++) acc[i][j] = 0.f;

    for (int k0 = 0; k0 < K; k0 += 16) {
#pragma unroll
        for (int it = 0; it < 2; it++) {
            int idx = tid + it * 256;
            int ar = idx >> 2;
            int ac = (idx & 3) * 4;
            float4 av = *(const float4*)(Ab + (size_t)ar * K + k0 + ac);
            As[(ac + 0) * 132 + ar] = av.x;
            As[(ac + 1) * 132 + ar] = av.y;
            As[(ac + 2) * 132 + ar] = av.z;
            As[(ac + 3) * 132 + ar] = av.w;
            int br = idx >> 5;
            int bc = (idx & 31) * 4;
            float4 bv = *(const float4*)(Bb + (size_t)(k0 + br) * N + bc);
            *(float4*)&Bs[br * 128 + bc] = bv;
        }
        __syncthreads();

#pragma unroll
        for (int k = 0; k < 16; k++) {
            float a[8], b[8];
            float4 a0 = *(const float4*)&As[k * 132 + ty * 8];
            float4 a1 = *(const float4*)&As[k * 132 + ty * 8 + 4];
            float4 b0 = *(const float4*)&Bs[k * 128 + tx * 8];
            float4 b1 = *(const float4*)&Bs[k * 128 + tx * 8 + 4];
            a[0]=a0.x; a[1]=a0.y; a[2]=a0.z; a[3]=a0.w;
            a[4]=a1.x; a[5]=a1.y; a[6]=a1.z; a[7]=a1.w;
            b[0]=b0.x; b[1]=b0.y; b[2]=b0.z; b[3]=b0.w;
            b[4]=b1.x; b[5]=b1.y; b[6]=b1.z; b[7]=b1.w;
#pragma unroll
            for (int i = 0; i < 8; i++)
#pragma unroll
                for (int j = 0; j < 8; j++)
                    acc[i][j] += a[i] * b[j];
        }
        __syncthreads();
    }

    const int col = bx * 128 + tx * 8;
    float4 bi0 = *(const float4*)(bias + col);
    float4 bi1 = *(const float4*)(bias + col + 4);
#pragma unroll
    for (int i = 0; i < 8; i++) {
        int row = by * 128 + ty * 8 + i;
        float4 o0, o1;
        o0.x = acc[i][0] + bi0.x; o0.y = acc[i][1] + bi0.y;
        o0.z = acc[i][2] + bi0.z; o0.w = acc[i][3] + bi0.w;
        o1.x = acc[i][4] + bi1.x; o1.y = acc[i][5] + bi1.y;
        o1.z = acc[i][6] + bi1.z; o1.w = acc[i][7] + bi1.w;
        *(float4*)(C + (size_t)row * N + col)     = o0;
        *(float4*)(C + (size_t)row * N + col + 4) = o1;
    }
}

// ---------------------------------------------------------------------------
// MQA flash attention (causal), fp32, cp.async double-buffered KV.
// Grid (S/128, NH, B), 512 threads. Q tile 128x128, KV sub-tiles 64x128.
// K stored k-chunk-major: Kt[k4][row] (float4), conflict-free, no padding.
// Phase A: warp w rows 8w..8w+7, lane cols {lane, lane+32}: 8x2 microtile.
// Phase B: thread rows 4ry..+3, dims {4dx..}, {64+4dx..}; P read as float4.
// ---------------------------------------------------------------------------
// smem floats: Qs 16384 | Kt 2*8192 | Vs 2*8192 | Ps 8192 | Cs 128 | Ls 128
#define Q_OFF   0
#define KT_OFF  16384
#define VS_OFF  (KT_OFF + 16384)
#define PS_OFF  (VS_OFF + 16384)
#define CS_OFF  (PS_OFF + 8192)
#define LS_OFF  (CS_OFF + 128)
#define ATT_SMEM ((LS_OFF + 128) * 4)      // 230400 B

__device__ __forceinline__ void issue_kv(
    uint32_t smb, int slot, const float* __restrict__ qkv,
    int b, int k0, int tid)
{
    const uint32_t kbase = smb + (KT_OFF + slot * 8192) * 4;
    const uint32_t vbase = smb + (VS_OFF + slot * 8192) * 4;
#pragma unroll
    for (int it = 0; it < 4; it++) {
        int c = tid + it * 512;            // 0..2047
        // K chunk: k4 = c>>6 (0..31), row = c&63 ; store at [k4][row]
        int kk4 = c >> 6, krow = c & 63;
        cp16(kbase + (uint32_t)(kk4 * 64 + krow) * 16,
             qkv + (size_t)(b * SS + k0 + krow) * QKV_N + HID + kk4 * 4);
        // V chunk: row = c>>5 (0..63), c16 = c&31 ; row-major pitch 128
        int vrow = c >> 5, vc = c & 31;
        cp16(vbase + (uint32_t)(vrow * 128 + vc * 4) * 4,
             qkv + (size_t)(b * SS + k0 + vrow) * QKV_N + HID + HD + vc * 4);
    }
    CP_COMMIT();
}

__global__ __launch_bounds__(512, 1) void mqa_kernel(
    const float* __restrict__ qkv, float* __restrict__ out)
{
    extern __shared__ float smf[];
    const uint32_t smb = smem_u32(smf);
    float* Qs = smf + Q_OFF;
    float* Ps = smf + PS_OFF;
    float* Cs = smf + CS_OFF;
    float* Ls = smf + LS_OFF;

    const int qt = (int)gridDim.x - 1 - (int)blockIdx.x;   // heavy tiles first
    const int h = blockIdx.y, b = blockIdx.z;
    const int tid = threadIdx.x;
    const int q0 = qt * 128;
    const float scale = 0.088388347648318447f;   // 1/sqrt(128)
    const int jmax = 2 * qt + 1;

    // start first KV load immediately, overlap with Q load
    issue_kv(smb, 0, qkv, b, 0, tid);

    // load Q tile (pitch 128; phase-A reads are broadcast so no pad needed)
    for (int i = tid; i < 128 * 32; i += 512) {
        int r = i >> 5, c4 = (i & 31) * 4;
        *(float4*)(Qs + r * 128 + c4) =
            *(const float4*)(qkv + (size_t)(b * SS + q0 + r) * QKV_N + h * HD + c4);
    }

    const int wid = tid >> 5, lane = tid & 31;   // phase A ids
    const int ry = tid >> 4, dx = tid & 15;      // phase B ids

    float m_i[8], l_i[8];
#pragma unroll
    for (int i = 0; i < 8; i++) { m_i[i] = -1e30f; l_i[i] = 0.f; }

    float acc[4][8];
#pragma unroll
    for (int i = 0; i < 4; i++)
#pragma unroll
        for (int j = 0; j < 8; j++) acc[i][j] = 0.f;

    for (int j = 0; j <= jmax; j++) {
        const int slot = j & 1;
        const int k0 = j * 64;

        // prefetch next sub-tile, then wait for current
        if (j < jmax) {
            issue_kv(smb, 1 - slot, qkv, b, k0 + 64, tid);
            CP_WAIT1();
        } else {
            CP_WAIT0();
        }
        __syncthreads();                 // K/V[slot] visible to all

        // -------- phase A: scores 8x2 microtile --------
        const float4* Kt4 = (const float4*)(smf + KT_OFF + slot * 8192);
        float s[8][2];
#pragma unroll
        for (int i = 0; i < 8; i++) { s[i][0] = 0.f; s[i][1] = 0.f; }

#pragma unroll 4
        for (int k4 = 0; k4 < 32; k4++) {
            float4 kk0 = Kt4[k4 * 64 + lane];
            float4 kk1 = Kt4[k4 * 64 + lane + 32];
#pragma unroll
            for (int i = 0; i < 8; i++) {
                float4 q = *(const float4*)(Qs + (8 * wid + i) * 128 + 4 * k4);
                s[i][0] += q.x * kk0.x + q.y * kk0.y + q.z * kk0.z + q.w * kk0.w;
                s[i][1] += q.x * kk1.x + q.y * kk1.y + q.z * kk1.z + q.w * kk1.w;
            }
        }

        const bool diag = (j >= 2 * qt);
        float corr[8];
#pragma unroll
        for (int i = 0; i < 8; i++) {
            const int row = q0 + 8 * wid + i;
            float v0 = s[i][0] * scale, v1 = s[i][1] * scale;
            if (diag) {
                if (k0 + lane      > row) v0 = -1e30f;
                if (k0 + lane + 32 > row) v1 = -1e30f;
            }
            float ml = fmaxf(v0, v1);
            ml = fmaxf(ml, __shfl_xor_sync(0xffffffffu, ml, 1));
            ml = fmaxf(ml, __shfl_xor_sync(0xffffffffu, ml, 2));
            ml = fmaxf(ml, __shfl_xor_sync(0xffffffffu, ml, 4));
            ml = fmaxf(ml, __shfl_xor_sync(0xffffffffu, ml, 8));
            ml = fmaxf(ml, __shfl_xor_sync(0xffffffffu, ml, 16));
            float mnew = fmaxf(m_i[i], ml);
            corr[i] = __expf(m_i[i] - mnew);
            float p0 = __expf(v0 - mnew);
            float p1 = __expf(v1 - mnew);
            s[i][0] = p0; s[i][1] = p1;
            float ps = p0 + p1;
            ps += __shfl_xor_sync(0xffffffffu, ps, 1);
            ps += __shfl_xor_sync(0xffffffffu, ps, 2);
            ps += __shfl_xor_sync(0xffffffffu, ps, 4);
            ps += __shfl_xor_sync(0xffffffffu, ps, 8);
            ps += __shfl_xor_sync(0xffffffffu, ps, 16);
            l_i[i] = l_i[i] * corr[i] + ps;
            m_i[i] = mnew;
        }

        // publish P (pitch 64), corr, running sums
#pragma unroll
        for (int i = 0; i < 8; i++) {
            Ps[(8 * wid + i) * 64 + lane]      = s[i][0];
            Ps[(8 * wid + i) * 64 + lane + 32] = s[i][1];
        }
        if (lane == 0) {
#pragma unroll
            for (int i = 0; i < 8; i++) {
                Cs[8 * wid + i] = corr[i];
                Ls[8 * wid + i] = l_i[i];
            }
        }
        __syncthreads();                 // P visible

        // -------- phase B: acc = acc*corr + P @ V --------
        const float* Vsf = smf + VS_OFF + slot * 8192;
#pragma unroll
        for (int i = 0; i < 4; i++) {
            float cr = Cs[4 * ry + i];
#pragma unroll
            for (int jj = 0; jj < 8; jj++) acc[i][jj] *= cr;
        }
#pragma unroll 2
        for (int c4 = 0; c4 < 16; c4++) {
            float4 pv[4];
#pragma unroll
            for (int i = 0; i < 4; i++)
                pv[i] = *(const float4*)(Ps + (4 * ry + i) * 64 + 4 * c4);
#pragma unroll
            for (int cc = 0; cc < 4; cc++) {
                const int c = 4 * c4 + cc;
                float4 v0 = *(const float4*)(Vsf + c * 128 + 4 * dx);
                float4 v1 = *(const float4*)(Vsf + c * 128 + 64 + 4 * dx);
#pragma unroll
                for (int i = 0; i < 4; i++) {
                    float p = (cc == 0) ? pv[i].x : (cc == 1) ? pv[i].y
                             : (cc == 2) ? pv[i].z : pv[i].w;
                    acc[i][0] += p * v0.x; acc[i][1] += p * v0.y;
                    acc[i][2] += p * v0.z; acc[i][3] += p * v0.w;
                    acc[i][4] += p * v1.x; acc[i][5] += p * v1.y;
                    acc[i][6] += p * v1.z; acc[i][7] += p * v1.w;
                }
            }
        }
        __syncthreads();                 // done with V[slot] / P before reuse
    }

    // epilogue
#pragma unroll
    for (int i = 0; i < 4; i++) {
        float linv = 1.f / Ls[4 * ry + i];
        int qg = q0 + 4 * ry + i;
        float* dst = out + (size_t)(b * SS + qg) * HID + h * HD;
        *(float4*)(dst + 4 * dx) = make_float4(
            acc[i][0] * linv, acc[i][1] * linv, acc[i][2] * linv, acc[i][3] * linv);
        *(float4*)(dst + 64 + 4 * dx) = make_float4(
            acc[i][4] * linv, acc[i][5] * linv, acc[i][6] * linv, acc[i][7] * linv);
    }
}

// ---------------------------------------------------------------------------
// kernel_launch
// ---------------------------------------------------------------------------
extern "C" void kernel_launch(void* const* d_in, const int* in_sizes, int n_in,
                              void* d_out, int out_size)
{
    const float* hidden = (const float*)d_in[0];
    const float* w1     = (const float*)d_in[2];
    const float* b1     = (const float*)d_in[3];
    const float* w2     = (const float*)d_in[4];
    const float* b2     = (const float*)d_in[5];
    float* out          = (float*)d_out;

    float *qkv, *att;
    cudaGetSymbolAddress((void**)&qkv, g_qkv);
    cudaGetSymbolAddress((void**)&att, g_att);

    cudaFuncSetAttribute(mqa_kernel, cudaFuncAttributeMaxDynamicSharedMemorySize, ATT_SMEM);

    // QKV projection
    dim3 g1(QKV_N / 128, MTOT / 128);
    sgemm_bias<<<g1, 256>>>(hidden, w1, b1, qkv, MTOT, QKV_N, HID);

    // attention
    mqa_kernel<<<dim3(SS / 128, NH, BB), 512, ATT_SMEM>>>(qkv, att);

    // output projection
    dim3 g2(HID / 128, MTOT / 128);
    sgemm_bias<<<g2, 256>>>(att, w2, b2, out, MTOT, HID, HID);
}

// round 15
// speedup vs baseline: 1.5632x; 1.0202x over previous
#include <cuda_runtime.h>
#include <cstdint>

#define HID   2048
#define NH    16
#define HD    128
#define QKV_N 2304
#define BB    2
#define SS    2048
#define MTOT  4096

// Scratch (no allocs allowed)
__device__ float g_qkv[(size_t)MTOT * QKV_N];
__device__ float g_att[(size_t)MTOT * HID];

// ---------------------------------------------------------------------------
// helpers
// ---------------------------------------------------------------------------
__device__ __forceinline__ uint32_t smem_u32(const void* p) {
    uint32_t a;
    asm("{ .reg .u64 t; cvta.to.shared.u64 t, %1; cvt.u32.u64 %0, t; }" : "=r"(a) : "l"(p));
    return a;
}
__device__ __forceinline__ void cp16(uint32_t s, const void* g) {
    asm volatile("cp.async.cg.shared.global [%0], [%1], 16;" :: "r"(s), "l"(g) : "memory");
}
#define CP_COMMIT() asm volatile("cp.async.commit_group;" ::: "memory")
#define CP_WAIT0()  asm volatile("cp.async.wait_group 0;" ::: "memory")

// ---------------------------------------------------------------------------
// SGEMM with bias: BM=BN=128, BK=16, 128 threads, 16x8 microtile.
// LDS traffic: 6 LDS.128 per 128 FFMA per thread (0.75 B/FMA).
// ---------------------------------------------------------------------------
__global__ __launch_bounds__(128, 2) void sgemm_bias(
    const float* __restrict__ A, const float* __restrict__ Bm,
    const float* __restrict__ bias, float* __restrict__ C,
    int M, int N, int K)
{
    __shared__ float As[16 * 132];   // transposed: As[k][m], padded
    __shared__ float Bs[16 * 128];   // Bs[k][n]

    const int bx = blockIdx.x;
    const int by = blockIdx.y;
    const int tid = threadIdx.x;
    const int tx = tid % 16;         // col group: cols tx*8..+7
    const int ty = tid / 16;         // row group: rows ty*16..+15

    const float* Ab = A + (size_t)by * 128 * K;
    const float* Bb = Bm + (size_t)bx * 128;

    float acc[16][8];
#pragma unroll
    for (int i = 0; i < 16; i++)
#pragma unroll
        for (int j = 0; j < 8; j++) acc[i][j] = 0.f;

    for (int k0 = 0; k0 < K; k0 += 16) {
#pragma unroll
        for (int it = 0; it < 4; it++) {
            int idx = tid + it * 128;          // 0..511
            int ar = idx >> 2;
            int ac = (idx & 3) * 4;
            float4 av = *(const float4*)(Ab + (size_t)ar * K + k0 + ac);
            As[(ac + 0) * 132 + ar] = av.x;
            As[(ac + 1) * 132 + ar] = av.y;
            As[(ac + 2) * 132 + ar] = av.z;
            As[(ac + 3) * 132 + ar] = av.w;
            int br = idx >> 5;
            int bc = (idx & 31) * 4;
            float4 bv = *(const float4*)(Bb + (size_t)(k0 + br) * N + bc);
            *(float4*)&Bs[br * 128 + bc] = bv;
        }
        __syncthreads();

#pragma unroll
        for (int k = 0; k < 16; k++) {
            float4 a0 = *(const float4*)&As[k * 132 + ty * 16];
            float4 a1 = *(const float4*)&As[k * 132 + ty * 16 + 4];
            float4 a2 = *(const float4*)&As[k * 132 + ty * 16 + 8];
            float4 a3 = *(const float4*)&As[k * 132 + ty * 16 + 12];
            float4 b0 = *(const float4*)&Bs[k * 128 + tx * 8];
            float4 b1 = *(const float4*)&Bs[k * 128 + tx * 8 + 4];
            float av[16] = {a0.x, a0.y, a0.z, a0.w, a1.x, a1.y, a1.z, a1.w,
                            a2.x, a2.y, a2.z, a2.w, a3.x, a3.y, a3.z, a3.w};
            float bv[8]  = {b0.x, b0.y, b0.z, b0.w, b1.x, b1.y, b1.z, b1.w};
#pragma unroll
            for (int i = 0; i < 16; i++)
#pragma unroll
                for (int j = 0; j < 8; j++)
                    acc[i][j] += av[i] * bv[j];
        }
        __syncthreads();
    }

    const int col = bx * 128 + tx * 8;
    float4 bi0 = *(const float4*)(bias + col);
    float4 bi1 = *(const float4*)(bias + col + 4);
#pragma unroll
    for (int i = 0; i < 16; i++) {
        int row = by * 128 + ty * 16 + i;
        float4 o0, o1;
        o0.x = acc[i][0] + bi0.x; o0.y = acc[i][1] + bi0.y;
        o0.z = acc[i][2] + bi0.z; o0.w = acc[i][3] + bi0.w;
        o1.x = acc[i][4] + bi1.x; o1.y = acc[i][5] + bi1.y;
        o1.z = acc[i][6] + bi1.z; o1.w = acc[i][7] + bi1.w;
        *(float4*)(C + (size_t)row * N + col)     = o0;
        *(float4*)(C + (size_t)row * N + col + 4) = o1;
    }
}

// ---------------------------------------------------------------------------
// MQA flash attention (causal), fp32, warp-autonomous subtiles.
// Grid (S/128, NH, B), 512 threads. Q tile 128x128, KV sub-tiles 64x128,
// cp.async double-buffered, ONE __syncthreads per subtile.
// Warp w owns rows 8w..8w+7 for phase A, softmax, P, phase B and epilogue.
// Phase A: lane owns cols {lane, lane+32} (s[8][2]).
// Phase B: lane owns dims 4*lane..4*lane+3 (acc[8][4]); P via own-row smem.
// ---------------------------------------------------------------------------
// smem floats: Qs 16384 | Kt 2*8192 | Vs 2*8192 | Ps 8192
#define Q_OFF   0
#define KT_OFF  16384
#define VS_OFF  (KT_OFF + 16384)
#define PS_OFF  (VS_OFF + 16384)
#define ATT_SMEM ((PS_OFF + 8192) * 4)     // 229376 B

__device__ __forceinline__ void issue_kv(
    uint32_t smb, int slot, const float* __restrict__ qkv,
    int b, int k0, int tid)
{
    const uint32_t kbase = smb + (KT_OFF + slot * 8192) * 4;
    const uint32_t vbase = smb + (VS_OFF + slot * 8192) * 4;
#pragma unroll
    for (int it = 0; it < 4; it++) {
        int c = tid + it * 512;            // 0..2047
        // K chunk: k4 = c>>6 (0..31), row = c&63 ; store at [k4][row]
        int kk4 = c >> 6, krow = c & 63;
        cp16(kbase + (uint32_t)(kk4 * 64 + krow) * 16,
             qkv + (size_t)(b * SS + k0 + krow) * QKV_N + HID + kk4 * 4);
        // V chunk: row = c>>5 (0..63), c16 = c&31 ; row-major pitch 128
        int vrow = c >> 5, vc = c & 31;
        cp16(vbase + (uint32_t)(vrow * 128 + vc * 4) * 4,
             qkv + (size_t)(b * SS + k0 + vrow) * QKV_N + HID + HD + vc * 4);
    }
    CP_COMMIT();
}

__global__ __launch_bounds__(512, 1) void mqa_kernel(
    const float* __restrict__ qkv, float* __restrict__ out)
{
    extern __shared__ float smf[];
    const uint32_t smb = smem_u32(smf);
    float* Qs = smf + Q_OFF;
    float* Ps = smf + PS_OFF;

    const int qt = (int)gridDim.x - 1 - (int)blockIdx.x;   // heavy tiles first
    const int h = blockIdx.y, b = blockIdx.z;
    const int tid = threadIdx.x;
    const int q0 = qt * 128;
    const float scale = 0.088388347648318447f;   // 1/sqrt(128)
    const int jmax = 2 * qt + 1;

    // start first KV load immediately, overlap with Q load
    issue_kv(smb, 0, qkv, b, 0, tid);

    // load Q tile (pitch 128; phase-A reads are broadcast so no pad needed)
    for (int i = tid; i < 128 * 32; i += 512) {
        int r = i >> 5, c4 = (i & 31) * 4;
        *(float4*)(Qs + r * 128 + c4) =
            *(const float4*)(qkv + (size_t)(b * SS + q0 + r) * QKV_N + h * HD + c4);
    }

    const int wid = tid >> 5, lane = tid & 31;
    const int r0 = 8 * wid;                      // warp's first row

    float m_i[8], l_i[8];
#pragma unroll
    for (int i = 0; i < 8; i++) { m_i[i] = -1e30f; l_i[i] = 0.f; }

    float acc[8][4];
#pragma unroll
    for (int i = 0; i < 8; i++)
#pragma unroll
        for (int d = 0; d < 4; d++) acc[i][d] = 0.f;

    for (int j = 0; j <= jmax; j++) {
        const int slot = j & 1;
        const int k0 = j * 64;

        CP_WAIT0();                  // this subtile's KV group complete
        __syncthreads();             // visibility; everyone done with old slot
        if (j < jmax)
            issue_kv(smb, 1 - slot, qkv, b, k0 + 64, tid);  // overlaps compute

        // -------- phase A: scores 8x2 microtile --------
        const float4* Kt4 = (const float4*)(smf + KT_OFF + slot * 8192);
        float s[8][2];
#pragma unroll
        for (int i = 0; i < 8; i++) { s[i][0] = 0.f; s[i][1] = 0.f; }

#pragma unroll 4
        for (int k4 = 0; k4 < 32; k4++) {
            float4 kk0 = Kt4[k4 * 64 + lane];
            float4 kk1 = Kt4[k4 * 64 + lane + 32];
#pragma unroll
            for (int i = 0; i < 8; i++) {
                float4 q = *(const float4*)(Qs + (r0 + i) * 128 + 4 * k4);
                s[i][0] += q.x * kk0.x + q.y * kk0.y + q.z * kk0.z + q.w * kk0.w;
                s[i][1] += q.x * kk1.x + q.y * kk1.y + q.z * kk1.z + q.w * kk1.w;
            }
        }

        // -------- softmax (in-warp, in-reg) --------
        const bool diag = (j >= 2 * qt);
        float corr[8];
#pragma unroll
        for (int i = 0; i < 8; i++) {
            const int row = q0 + r0 + i;
            float v0 = s[i][0] * scale, v1 = s[i][1] * scale;
            if (diag) {
                if (k0 + lane      > row) v0 = -1e30f;
                if (k0 + lane + 32 > row) v1 = -1e30f;
            }
            float ml = fmaxf(v0, v1);
            ml = fmaxf(ml, __shfl_xor_sync(0xffffffffu, ml, 1));
            ml = fmaxf(ml, __shfl_xor_sync(0xffffffffu, ml, 2));
            ml = fmaxf(ml, __shfl_xor_sync(0xffffffffu, ml, 4));
            ml = fmaxf(ml, __shfl_xor_sync(0xffffffffu, ml, 8));
            ml = fmaxf(ml, __shfl_xor_sync(0xffffffffu, ml, 16));
            float mnew = fmaxf(m_i[i], ml);
            corr[i] = __expf(m_i[i] - mnew);
            float p0 = __expf(v0 - mnew);
            float p1 = __expf(v1 - mnew);
            s[i][0] = p0; s[i][1] = p1;
            float ps = p0 + p1;
            ps += __shfl_xor_sync(0xffffffffu, ps, 1);
            ps += __shfl_xor_sync(0xffffffffu, ps, 2);
            ps += __shfl_xor_sync(0xffffffffu, ps, 4);
            ps += __shfl_xor_sync(0xffffffffu, ps, 8);
            ps += __shfl_xor_sync(0xffffffffu, ps, 16);
            l_i[i] = l_i[i] * corr[i] + ps;
            m_i[i] = mnew;
        }

        // publish P to own rows (pitch 64) — in-warp transpose via smem
#pragma unroll
        for (int i = 0; i < 8; i++) {
            Ps[(r0 + i) * 64 + lane]      = s[i][0];
            Ps[(r0 + i) * 64 + lane + 32] = s[i][1];
        }
        __syncwarp();

        // -------- phase B: acc = acc*corr + P @ V  (own rows only) --------
#pragma unroll
        for (int i = 0; i < 8; i++) {
#pragma unroll
            for (int d = 0; d < 4; d++) acc[i][d] *= corr[i];
        }
        const float* Vsf = smf + VS_OFF + slot * 8192;
#pragma unroll 2
        for (int c4 = 0; c4 < 16; c4++) {
            float4 v[4];
#pragma unroll
            for (int cc = 0; cc < 4; cc++)
                v[cc] = *(const float4*)(Vsf + (4 * c4 + cc) * 128 + 4 * lane);
#pragma unroll
            for (int hf = 0; hf < 2; hf++) {
                float4 pv[4];
#pragma unroll
                for (int i4 = 0; i4 < 4; i4++)
                    pv[i4] = *(const float4*)(Ps + (r0 + 4 * hf + i4) * 64 + 4 * c4);
#pragma unroll
                for (int i4 = 0; i4 < 4; i4++) {
                    const int i = 4 * hf + i4;
                    acc[i][0] += pv[i4].x * v[0].x; acc[i][1] += pv[i4].x * v[0].y;
                    acc[i][2] += pv[i4].x * v[0].z; acc[i][3] += pv[i4].x * v[0].w;
                    acc[i][0] += pv[i4].y * v[1].x; acc[i][1] += pv[i4].y * v[1].y;
                    acc[i][2] += pv[i4].y * v[1].z; acc[i][3] += pv[i4].y * v[1].w;
                    acc[i][0] += pv[i4].z * v[2].x; acc[i][1] += pv[i4].z * v[2].y;
                    acc[i][2] += pv[i4].z * v[2].z; acc[i][3] += pv[i4].z * v[2].w;
                    acc[i][0] += pv[i4].w * v[3].x; acc[i][1] += pv[i4].w * v[3].y;
                    acc[i][2] += pv[i4].w * v[3].z; acc[i][3] += pv[i4].w * v[3].w;
                }
            }
        }
    }

    // epilogue (all state in-warp)
#pragma unroll
    for (int i = 0; i < 8; i++) {
        float linv = 1.f / l_i[i];
        int qg = q0 + r0 + i;
        float* dst = out + (size_t)(b * SS + qg) * HID + h * HD + 4 * lane;
        *(float4*)dst = make_float4(acc[i][0] * linv, acc[i][1] * linv,
                                    acc[i][2] * linv, acc[i][3] * linv);
    }
}

// ---------------------------------------------------------------------------
// kernel_launch
// ---------------------------------------------------------------------------
extern "C" void kernel_launch(void* const* d_in, const int* in_sizes, int n_in,
                              void* d_out, int out_size)
{
    const float* hidden = (const float*)d_in[0];
    const float* w1     = (const float*)d_in[2];
    const float* b1     = (const float*)d_in[3];
    const float* w2     = (const float*)d_in[4];
    const float* b2     = (const float*)d_in[5];
    float* out          = (float*)d_out;

    float *qkv, *att;
    cudaGetSymbolAddress((void**)&qkv, g_qkv);
    cudaGetSymbolAddress((void**)&att, g_att);

    cudaFuncSetAttribute(mqa_kernel, cudaFuncAttributeMaxDynamicSharedMemorySize, ATT_SMEM);

    // QKV projection
    dim3 g1(QKV_N / 128, MTOT / 128);
    sgemm_bias<<<g1, 128>>>(hidden, w1, b1, qkv, MTOT, QKV_N, HID);

    // attention
    mqa_kernel<<<dim3(SS / 128, NH, BB), 512, ATT_SMEM>>>(qkv, att);

    // output projection
    dim3 g2(HID / 128, MTOT / 128);
    sgemm_bias<<<g2, 128>>>(att, w2, b2, out, MTOT, HID, HID);
}

// round 16
// speedup vs baseline: 1.6146x; 1.0329x over previous
#include <cuda_runtime.h>
#include <cstdint>

#define HID   2048
#define NH    16
#define HD    128
#define QKV_N 2304
#define BB    2
#define SS    2048
#define MTOT  4096

// Scratch (no allocs allowed)
__device__ float g_qkv[(size_t)MTOT * QKV_N];
__device__ float g_att[(size_t)MTOT * HID];

// ---------------------------------------------------------------------------
// helpers
// ---------------------------------------------------------------------------
__device__ __forceinline__ uint32_t smem_u32(const void* p) {
    uint32_t a;
    asm("{ .reg .u64 t; cvta.to.shared.u64 t, %1; cvt.u32.u64 %0, t; }" : "=r"(a) : "l"(p));
    return a;
}
__device__ __forceinline__ void cp16(uint32_t s, const void* g) {
    asm volatile("cp.async.cg.shared.global [%0], [%1], 16;" :: "r"(s), "l"(g) : "memory");
}
#define CP_COMMIT() asm volatile("cp.async.commit_group;" ::: "memory")
#define CP_WAIT0()  asm volatile("cp.async.wait_group 0;" ::: "memory")

// ---------------------------------------------------------------------------
// SGEMM with bias: BM=BN=128, BK=16, 256 threads, 8x8 microtile.
// Microtile columns split as {tx*4..+3} and {64+tx*4..+3} so B fragment
// LDS.128s are bank-conflict-free (16B lane stride spans all 32 banks).
// ---------------------------------------------------------------------------
__global__ __launch_bounds__(256) void sgemm_bias(
    const float* __restrict__ A, const float* __restrict__ Bm,
    const float* __restrict__ bias, float* __restrict__ C,
    int M, int N, int K)
{
    __shared__ float As[16 * 132];   // transposed: As[k][m], padded
    __shared__ float Bs[16 * 128];   // Bs[k][n]

    const int bx = blockIdx.x;
    const int by = blockIdx.y;
    const int tid = threadIdx.x;
    const int tx = tid % 16;
    const int ty = tid / 16;

    const float* Ab = A + (size_t)by * 128 * K;
    const float* Bb = Bm + (size_t)bx * 128;

    float acc[8][8];
#pragma unroll
    for (int i = 0; i < 8; i++)
#pragma unroll
        for (int j = 0; j < 8; j++) acc[i][j] = 0.f;

    for (int k0 = 0; k0 < K; k0 += 16) {
#pragma unroll
        for (int it = 0; it < 2; it++) {
            int idx = tid + it * 256;
            int ar = idx >> 2;
            int ac = (idx & 3) * 4;
            float4 av = *(const float4*)(Ab + (size_t)ar * K + k0 + ac);
            As[(ac + 0) * 132 + ar] = av.x;
            As[(ac + 1) * 132 + ar] = av.y;
            As[(ac + 2) * 132 + ar] = av.z;
            As[(ac + 3) * 132 + ar] = av.w;
            int br = idx >> 5;
            int bc = (idx & 31) * 4;
            float4 bv = *(const float4*)(Bb + (size_t)(k0 + br) * N + bc);
            *(float4*)&Bs[br * 128 + bc] = bv;
        }
        __syncthreads();

#pragma unroll
        for (int k = 0; k < 16; k++) {
            float a[8], b[8];
            float4 a0 = *(const float4*)&As[k * 132 + ty * 8];
            float4 a1 = *(const float4*)&As[k * 132 + ty * 8 + 4];
            float4 b0 = *(const float4*)&Bs[k * 128 + tx * 4];        // conflict-free
            float4 b1 = *(const float4*)&Bs[k * 128 + 64 + tx * 4];   // conflict-free
            a[0]=a0.x; a[1]=a0.y; a[2]=a0.z; a[3]=a0.w;
            a[4]=a1.x; a[5]=a1.y; a[6]=a1.z; a[7]=a1.w;
            b[0]=b0.x; b[1]=b0.y; b[2]=b0.z; b[3]=b0.w;
            b[4]=b1.x; b[5]=b1.y; b[6]=b1.z; b[7]=b1.w;
#pragma unroll
            for (int i = 0; i < 8; i++)
#pragma unroll
                for (int j = 0; j < 8; j++)
                    acc[i][j] += a[i] * b[j];
        }
        __syncthreads();
    }

    const int col = bx * 128 + tx * 4;
    float4 bi0 = *(const float4*)(bias + col);
    float4 bi1 = *(const float4*)(bias + col + 64);
#pragma unroll
    for (int i = 0; i < 8; i++) {
        int row = by * 128 + ty * 8 + i;
        float4 o0, o1;
        o0.x = acc[i][0] + bi0.x; o0.y = acc[i][1] + bi0.y;
        o0.z = acc[i][2] + bi0.z; o0.w = acc[i][3] + bi0.w;
        o1.x = acc[i][4] + bi1.x; o1.y = acc[i][5] + bi1.y;
        o1.z = acc[i][6] + bi1.z; o1.w = acc[i][7] + bi1.w;
        *(float4*)(C + (size_t)row * N + col)      = o0;
        *(float4*)(C + (size_t)row * N + col + 64) = o1;
    }
}

// ---------------------------------------------------------------------------
// MQA flash attention (causal), fp32, warp-autonomous subtiles.
// (unchanged from R15 — best measured)
// ---------------------------------------------------------------------------
// smem floats: Qs 16384 | Kt 2*8192 | Vs 2*8192 | Ps 8192
#define Q_OFF   0
#define KT_OFF  16384
#define VS_OFF  (KT_OFF + 16384)
#define PS_OFF  (VS_OFF + 16384)
#define ATT_SMEM ((PS_OFF + 8192) * 4)     // 229376 B

__device__ __forceinline__ void issue_kv(
    uint32_t smb, int slot, const float* __restrict__ qkv,
    int b, int k0, int tid)
{
    const uint32_t kbase = smb + (KT_OFF + slot * 8192) * 4;
    const uint32_t vbase = smb + (VS_OFF + slot * 8192) * 4;
#pragma unroll
    for (int it = 0; it < 4; it++) {
        int c = tid + it * 512;            // 0..2047
        int kk4 = c >> 6, krow = c & 63;
        cp16(kbase + (uint32_t)(kk4 * 64 + krow) * 16,
             qkv + (size_t)(b * SS + k0 + krow) * QKV_N + HID + kk4 * 4);
        int vrow = c >> 5, vc = c & 31;
        cp16(vbase + (uint32_t)(vrow * 128 + vc * 4) * 4,
             qkv + (size_t)(b * SS + k0 + vrow) * QKV_N + HID + HD + vc * 4);
    }
    CP_COMMIT();
}

__global__ __launch_bounds__(512, 1) void mqa_kernel(
    const float* __restrict__ qkv, float* __restrict__ out)
{
    extern __shared__ float smf[];
    const uint32_t smb = smem_u32(smf);
    float* Qs = smf + Q_OFF;
    float* Ps = smf + PS_OFF;

    const int qt = (int)gridDim.x - 1 - (int)blockIdx.x;   // heavy tiles first
    const int h = blockIdx.y, b = blockIdx.z;
    const int tid = threadIdx.x;
    const int q0 = qt * 128;
    const float scale = 0.088388347648318447f;   // 1/sqrt(128)
    const int jmax = 2 * qt + 1;

    issue_kv(smb, 0, qkv, b, 0, tid);

    for (int i = tid; i < 128 * 32; i += 512) {
        int r = i >> 5, c4 = (i & 31) * 4;
        *(float4*)(Qs + r * 128 + c4) =
            *(const float4*)(qkv + (size_t)(b * SS + q0 + r) * QKV_N + h * HD + c4);
    }

    const int wid = tid >> 5, lane = tid & 31;
    const int r0 = 8 * wid;

    float m_i[8], l_i[8];
#pragma unroll
    for (int i = 0; i < 8; i++) { m_i[i] = -1e30f; l_i[i] = 0.f; }

    float acc[8][4];
#pragma unroll
    for (int i = 0; i < 8; i++)
#pragma unroll
        for (int d = 0; d < 4; d++) acc[i][d] = 0.f;

    for (int j = 0; j <= jmax; j++) {
        const int slot = j & 1;
        const int k0 = j * 64;

        CP_WAIT0();
        __syncthreads();
        if (j < jmax)
            issue_kv(smb, 1 - slot, qkv, b, k0 + 64, tid);

        // -------- phase A: scores 8x2 microtile --------
        const float4* Kt4 = (const float4*)(smf + KT_OFF + slot * 8192);
        float s[8][2];
#pragma unroll
        for (int i = 0; i < 8; i++) { s[i][0] = 0.f; s[i][1] = 0.f; }

#pragma unroll 4
        for (int k4 = 0; k4 < 32; k4++) {
            float4 kk0 = Kt4[k4 * 64 + lane];
            float4 kk1 = Kt4[k4 * 64 + lane + 32];
#pragma unroll
            for (int i = 0; i < 8; i++) {
                float4 q = *(const float4*)(Qs + (r0 + i) * 128 + 4 * k4);
                s[i][0] += q.x * kk0.x + q.y * kk0.y + q.z * kk0.z + q.w * kk0.w;
                s[i][1] += q.x * kk1.x + q.y * kk1.y + q.z * kk1.z + q.w * kk1.w;
            }
        }

        // -------- softmax (in-warp, in-reg) --------
        const bool diag = (j >= 2 * qt);
        float corr[8];
#pragma unroll
        for (int i = 0; i < 8; i++) {
            const int row = q0 + r0 + i;
            float v0 = s[i][0] * scale, v1 = s[i][1] * scale;
            if (diag) {
                if (k0 + lane      > row) v0 = -1e30f;
                if (k0 + lane + 32 > row) v1 = -1e30f;
            }
            float ml = fmaxf(v0, v1);
            ml = fmaxf(ml, __shfl_xor_sync(0xffffffffu, ml, 1));
            ml = fmaxf(ml, __shfl_xor_sync(0xffffffffu, ml, 2));
            ml = fmaxf(ml, __shfl_xor_sync(0xffffffffu, ml, 4));
            ml = fmaxf(ml, __shfl_xor_sync(0xffffffffu, ml, 8));
            ml = fmaxf(ml, __shfl_xor_sync(0xffffffffu, ml, 16));
            float mnew = fmaxf(m_i[i], ml);
            corr[i] = __expf(m_i[i] - mnew);
            float p0 = __expf(v0 - mnew);
            float p1 = __expf(v1 - mnew);
            s[i][0] = p0; s[i][1] = p1;
            float ps = p0 + p1;
            ps += __shfl_xor_sync(0xffffffffu, ps, 1);
            ps += __shfl_xor_sync(0xffffffffu, ps, 2);
            ps += __shfl_xor_sync(0xffffffffu, ps, 4);
            ps += __shfl_xor_sync(0xffffffffu, ps, 8);
            ps += __shfl_xor_sync(0xffffffffu, ps, 16);
            l_i[i] = l_i[i] * corr[i] + ps;
            m_i[i] = mnew;
        }

        // publish P to own rows (pitch 64)
#pragma unroll
        for (int i = 0; i < 8; i++) {
            Ps[(r0 + i) * 64 + lane]      = s[i][0];
            Ps[(r0 + i) * 64 + lane + 32] = s[i][1];
        }
        __syncwarp();

        // -------- phase B: acc = acc*corr + P @ V  (own rows only) --------
#pragma unroll
        for (int i = 0; i < 8; i++) {
#pragma unroll
            for (int d = 0; d < 4; d++) acc[i][d] *= corr[i];
        }
        const float* Vsf = smf + VS_OFF + slot * 8192;
#pragma unroll 2
        for (int c4 = 0; c4 < 16; c4++) {
            float4 v[4];
#pragma unroll
            for (int cc = 0; cc < 4; cc++)
                v[cc] = *(const float4*)(Vsf + (4 * c4 + cc) * 128 + 4 * lane);
#pragma unroll
            for (int hf = 0; hf < 2; hf++) {
                float4 pv[4];
#pragma unroll
                for (int i4 = 0; i4 < 4; i4++)
                    pv[i4] = *(const float4*)(Ps + (r0 + 4 * hf + i4) * 64 + 4 * c4);
#pragma unroll
                for (int i4 = 0; i4 < 4; i4++) {
                    const int i = 4 * hf + i4;
                    acc[i][0] += pv[i4].x * v[0].x; acc[i][1] += pv[i4].x * v[0].y;
                    acc[i][2] += pv[i4].x * v[0].z; acc[i][3] += pv[i4].x * v[0].w;
                    acc[i][0] += pv[i4].y * v[1].x; acc[i][1] += pv[i4].y * v[1].y;
                    acc[i][2] += pv[i4].y * v[1].z; acc[i][3] += pv[i4].y * v[1].w;
                    acc[i][0] += pv[i4].z * v[2].x; acc[i][1] += pv[i4].z * v[2].y;
                    acc[i][2] += pv[i4].z * v[2].z; acc[i][3] += pv[i4].z * v[2].w;
                    acc[i][0] += pv[i4].w * v[3].x; acc[i][1] += pv[i4].w * v[3].y;
                    acc[i][2] += pv[i4].w * v[3].z; acc[i][3] += pv[i4].w * v[3].w;
                }
            }
        }
    }

    // epilogue (all state in-warp)
#pragma unroll
    for (int i = 0; i < 8; i++) {
        float linv = 1.f / l_i[i];
        int qg = q0 + r0 + i;
        float* dst = out + (size_t)(b * SS + qg) * HID + h * HD + 4 * lane;
        *(float4*)dst = make_float4(acc[i][0] * linv, acc[i][1] * linv,
                                    acc[i][2] * linv, acc[i][3] * linv);
    }
}

// ---------------------------------------------------------------------------
// kernel_launch
// ---------------------------------------------------------------------------
extern "C" void kernel_launch(void* const* d_in, const int* in_sizes, int n_in,
                              void* d_out, int out_size)
{
    const float* hidden = (const float*)d_in[0];
    const float* w1     = (const float*)d_in[2];
    const float* b1     = (const float*)d_in[3];
    const float* w2     = (const float*)d_in[4];
    const float* b2     = (const float*)d_in[5];
    float* out          = (float*)d_out;

    float *qkv, *att;
    cudaGetSymbolAddress((void**)&qkv, g_qkv);
    cudaGetSymbolAddress((void**)&att, g_att);

    cudaFuncSetAttribute(mqa_kernel, cudaFuncAttributeMaxDynamicSharedMemorySize, ATT_SMEM);

    // QKV projection
    dim3 g1(QKV_N / 128, MTOT / 128);
    sgemm_bias<<<g1, 256>>>(hidden, w1, b1, qkv, MTOT, QKV_N, HID);

    // attention
    mqa_kernel<<<dim3(SS / 128, NH, BB), 512, ATT_SMEM>>>(qkv, att);

    // output projection
    dim3 g2(HID / 128, MTOT / 128);
    sgemm_bias<<<g2, 256>>>(att, w2, b2, out, MTOT, HID, HID);
}